// round 6
// baseline (speedup 1.0000x reference)
#include <cuda_runtime.h>
#include <cstdint>

#define CAPL   65536
#define NMSCAP 5000
#define NEGV   (-1000000000.0f)
#define BBOXCL 4.135166556742356f

typedef unsigned long long ull;

// ------------------------- device scratch (no allocs) -----------------------
__device__ float g_t0[10376704];
__device__ float g_t1[10376704];
__device__ float g_t2[10376704];
__device__ float g_t3[10376704];
__device__ float g_reg[1459224];
__device__ float g_mu[640];
__device__ float g_var[640];
__device__ ull   g_k64[10 * CAPL];
__device__ int   g_cnt[10];
__device__ float g_nbox[2 * NMSCAP * 4];

__constant__ int  c_Hs[5]    = {100, 50, 25, 13, 7};
__constant__ int  c_Ws[5]    = {152, 76, 38, 19, 10};
__constant__ int  c_HW[5]    = {15200, 3800, 950, 247, 70};
__constant__ long c_lb[5]    = {0, 7782400, 9728000, 10214400, 10340864};
__constant__ long c_regoff[5] = {0, 1094400, 1368000, 1436400, 1454184};
__constant__ int  c_ancoff[5] = {0, 136800, 171000, 179550, 181773};
__constant__ int  c_cum[5]   = {247, 317, 337, 343, 345};
__constant__ int  c_tw[5]    = {19, 10, 5, 3, 2};

__device__ __forceinline__ float* tb(int id) {
    switch (id) {
        case 0: return g_t0;
        case 1: return g_t1;
        case 2: return g_t2;
        default: return g_t3;
    }
}

// ------------------------- candidate emit -----------------------------------
__device__ __forceinline__ void emit_cand(float v, int oc, int s, int n, int lvl) {
    float sg = 1.0f / (1.0f + expf(-v));
    if (sg > 0.05f) {
        int a = oc / 91, c = oc - 91 * a;
        unsigned flat = (unsigned)((s * 9 + a) * 91 + c);
        unsigned key  = ((unsigned)lvl << 24) | flat;
        int pos = atomicAdd(&g_cnt[n * 5 + lvl], 1);
        if (pos < CAPL)
            g_k64[(long)(n * 5 + lvl) * CAPL + pos] =
                (((ull)(0xFFFFFFFFu - __float_as_uint(sg))) << 32) | key;
    }
}

// ------------------------- merged conv 3x3 SAME, Cin=256, fp32 --------------
// block 256 thr = 64 oc x (8x8 px); per-thread 4 oc x 4 px.
// ymode: 0 = tower write, 1 = cls candidate emit, 2 = reg-head write
__global__ __launch_bounds__(256, 4) void conv_m(
    const float* __restrict__ x0, const float* __restrict__ x1,
    const float* __restrict__ x2, const float* __restrict__ x3,
    const float* __restrict__ x4,
    int xpp, int ymode, int ypp,
    const float* __restrict__ wA, const float* __restrict__ wB,
    const float* __restrict__ bA, const float* __restrict__ bB,
    const float* __restrict__ gsA, const float* __restrict__ gbA,
    const float* __restrict__ gsB, const float* __restrict__ gbB,
    int gnflag, int OC, int OCT, int NBR, int brfix)
{
    __shared__ float xs[16 * 120];                 // 16 ic x 10 rows (stride 12)
    __shared__ __align__(16) float ws[144 * 68];   // [ic*9+tap][oc]
    __shared__ float scl[256], shb[256];

    // ---- block decomposition: oct fastest ----
    int bid = blockIdx.x;
    const int oct = bid % OCT;  bid /= OCT;
    const int tile = bid % 345; bid /= 345;
    const int n = bid % 2;      bid /= 2;
    const int br = (NBR == 2) ? bid : brfix;

    int l = 0;
    while (tile >= c_cum[l]) l++;
    const int ltile = tile - (l ? c_cum[l - 1] : 0);
    const int H = c_Hs[l], W = c_Ws[l], HW = c_HW[l];
    const int h0 = (ltile / c_tw[l]) * 8;
    const int w0 = (ltile % c_tw[l]) * 8;
    const int oc0 = oct * 64;

    const float* wgt = br ? wB : wA;
    const float* bias = br ? bB : bA;

    const float* x;
    if (xpp < 0) {
        x = (l == 0) ? x0 : (l == 1) ? x1 : (l == 2) ? x2 : (l == 3) ? x3 : x4;
    } else {
        x = tb(br * 2 + xpp) + c_lb[l];
    }

    const int t = threadIdx.x;
    const int oc_id = t >> 4;            // 0..15 (4 oc each)
    const int px_id = t & 15;
    const int ph  = px_id >> 1;          // 0..7
    const int pw0 = (px_id & 1) * 4;     // 0 or 4

    // weight staging decomposition (div-free)
    const int woc = t >> 2;              // 0..63
    const int wq  = t & 3;               // 0..3 -> taps [wq*36, wq*36+36)

    // per-channel folded GN scale/shift
    {
        const int c = t;
        if (gnflag) {
            const float* gs = br ? gsB : gsA;
            const float* gb = br ? gbB : gbA;
            int m = ((br * 5 + l) * 2 + n) * 32 + (c >> 3);
            float s2 = rsqrtf(g_var[m] + 1e-5f) * gs[c];
            scl[c] = s2;
            shb[c] = gb[c] - g_mu[m] * s2;
        } else { scl[c] = 1.f; shb[c] = 0.f; }
    }
    __syncthreads();

    float acc[4][4] = {};

    for (int ic0 = 0; ic0 < 256; ic0 += 16) {
        // ---- input window: 16 ic x 10x10 (stride 12), zero pad, fused GN+ReLU
        for (int d = t; d < 1600; d += 256) {
            int ic = d / 100, r = d - ic * 100;
            int iy = r / 10, ix = r - iy * 10;
            int gy = h0 - 1 + iy, gx = w0 - 1 + ix;
            float v = 0.f;
            if ((unsigned)gy < (unsigned)H && (unsigned)gx < (unsigned)W) {
                v = x[(long)(n * 256 + ic0 + ic) * HW + gy * W + gx];
                if (gnflag) v = fmaxf(v * scl[ic0 + ic] + shb[ic0 + ic], 0.f);
            }
            xs[ic * 120 + iy * 12 + ix] = v;
        }
        // ---- weights: 64 oc x 144 taps, div-free, LDG.128 ----
        {
            const int oca = oc0 + woc;
            if (oca < OC) {
                const float4* src = reinterpret_cast<const float4*>(
                    wgt + (long)oca * 2304 + ic0 * 9 + wq * 36);
#pragma unroll
                for (int i = 0; i < 9; i++) {
                    float4 v = src[i];
                    float* wp = ws + (wq * 36 + i * 4) * 68 + woc;
                    wp[0]   = v.x;
                    wp[68]  = v.y;
                    wp[136] = v.z;
                    wp[204] = v.w;
                }
            } else {
#pragma unroll
                for (int i = 0; i < 36; i++) ws[(wq * 36 + i) * 68 + woc] = 0.f;
            }
        }
        __syncthreads();

        const float* xbase = xs + ph * 12 + pw0;
        const float* wbase = ws + (oc_id << 2);
#pragma unroll 8
        for (int ic = 0; ic < 16; ic++) {
#pragma unroll
            for (int ky = 0; ky < 3; ky++) {
                const float* row = xbase + ic * 120 + ky * 12;
                float4 a4 = *reinterpret_cast<const float4*>(row);
                float2 b2 = *reinterpret_cast<const float2*>(row + 4);
                float xv[6] = {a4.x, a4.y, a4.z, a4.w, b2.x, b2.y};
#pragma unroll
                for (int kx = 0; kx < 3; kx++) {
                    const float4 wv = *reinterpret_cast<const float4*>(
                        wbase + (ic * 9 + ky * 3 + kx) * 68);
#pragma unroll
                    for (int j = 0; j < 4; j++) {
                        acc[0][j] += wv.x * xv[kx + j];
                        acc[1][j] += wv.y * xv[kx + j];
                        acc[2][j] += wv.z * xv[kx + j];
                        acc[3][j] += wv.w * xv[kx + j];
                    }
                }
            }
        }
        __syncthreads();
    }

    // ---- epilogue ----
    const int h = h0 + ph;
    if (h < H) {
        float* y = (ymode == 0) ? tb(br * 2 + ypp) + c_lb[l]
                 : (ymode == 2) ? g_reg + c_regoff[l] : nullptr;
#pragma unroll
        for (int i = 0; i < 4; i++) {
            int oc = oc0 + (oc_id << 2) + i;
            if (oc < OC) {
                float bv = bias[oc];
#pragma unroll
                for (int j = 0; j < 4; j++) {
                    int w = w0 + pw0 + j;
                    if (w < W) {
                        float v = acc[i][j] + bv;
                        if (ymode == 1) {
                            if (v > -3.0f) emit_cand(v, oc, h * W + w, n, l);
                        } else if (ymode == 0) {
                            y[(long)(n * 256 + oc) * HW + h * W + w] = v;
                        } else {
                            y[(long)(n * 36 + oc) * HW + h * W + w] = v;
                        }
                    }
                }
            }
        }
    }
}

// ------------------------- merged GroupNorm stats ---------------------------
__global__ __launch_bounds__(256) void gn_stats_m(int pp)
{
    int b = blockIdx.x;
    const int g = b % 32; b /= 32;
    const int n = b % 2;  b /= 2;
    const int l = b % 5;  b /= 5;
    const int br = b;
    const int HW = c_HW[l];
    const float* p = tb(br * 2 + pp) + c_lb[l] + (long)(n * 256 + g * 8) * HW;
    const int total = 8 * HW;
    double s = 0.0, ss = 0.0;
    for (int i = threadIdx.x; i < total; i += 256) {
        float v = p[i];
        s += v; ss += (double)v * (double)v;
    }
    __shared__ double rs[256], rq[256];
    rs[threadIdx.x] = s; rq[threadIdx.x] = ss;
    __syncthreads();
    for (int o = 128; o; o >>= 1) {
        if (threadIdx.x < o) { rs[threadIdx.x] += rs[threadIdx.x+o]; rq[threadIdx.x] += rq[threadIdx.x+o]; }
        __syncthreads();
    }
    if (threadIdx.x == 0) {
        int m = ((br * 5 + l) * 2 + n) * 32 + g;
        double mu = rs[0] / total;
        g_mu[m]  = (float)mu;
        g_var[m] = (float)(rq[0] / total - mu * mu);
    }
}

// ------------------------- sort / nms ----------------------------------------
__global__ void zero_cnt() { if (threadIdx.x < 10) g_cnt[threadIdx.x] = 0; }

__global__ __launch_bounds__(1024) void sort_k()
{
    const int b = blockIdx.x;
    ull* v = g_k64 + (long)b * CAPL;
    int cnt = g_cnt[b]; if (cnt > CAPL) cnt = CAPL;
    if (cnt <= 1) return;
    int n2 = 1; while (n2 < cnt) n2 <<= 1;
    for (int i = cnt + threadIdx.x; i < n2; i += 1024) v[i] = ~0ull;
    __syncthreads();
    for (int k = 2; k <= n2; k <<= 1) {
        for (int j = k >> 1; j > 0; j >>= 1) {
            for (int i = threadIdx.x; i < n2; i += 1024) {
                int ixj = i ^ j;
                if (ixj > i) {
                    ull a = v[i], c2 = v[ixj];
                    if ((a > c2) == ((i & k) == 0)) { v[i] = c2; v[ixj] = a; }
                }
            }
            __syncthreads();
        }
    }
}

extern __shared__ unsigned char s_raw[];

__global__ __launch_bounds__(256) void nms_k(const float* __restrict__ anc,
                                             float* __restrict__ out)
{
    const int n = blockIdx.x;
    float*    sws  = (float*)s_raw;
    float*    sbo  = (float*)s_raw + 5008;
    unsigned* skey = (unsigned*)((float*)s_raw + 25008);
    __shared__ float rbs[256];
    __shared__ unsigned rbk[256];
    __shared__ int rbi[256];

    int Ls[5], offs[5], K = 0;
    for (int l = 0; l < 5; l++) {
        int c = g_cnt[n * 5 + l];
        if (c > CAPL) c = CAPL;
        if (c > 1000) c = 1000;
        offs[l] = K; Ls[l] = c; K += c;
    }

    for (int idx = threadIdx.x; idx < K; idx += 256) {
        int l = 0;
        while (l < 4 && idx >= offs[l] + Ls[l]) l++;
        int kin = idx - offs[l];
        ull v = g_k64[(long)(n * 5 + l) * CAPL + kin];
        unsigned key = (unsigned)v;
        float sc = __uint_as_float(0xFFFFFFFFu - (unsigned)(v >> 32));
        int flat = (int)(key & 0xFFFFFFu);
        int ai = flat / 91, c = flat - ai * 91;
        int sidx = ai / 9, a = ai - sidx * 9;
        int HW = c_HW[l];
        const float* rp = g_reg + c_regoff[l] + (long)(n * 36 + a * 4) * HW + sidx;
        float dx = rp[0], dy = rp[HW], dw = rp[2*HW], dh = rp[3*HW];
        int gidx = c_ancoff[l] + ai;
        float ax0 = anc[4*gidx], ay0 = anc[4*gidx+1], ax1 = anc[4*gidx+2], ay1 = anc[4*gidx+3];
        float aw = ax1 - ax0, ah = ay1 - ay0;
        float cx = ax0 + 0.5f * aw, cy = ay0 + 0.5f * ah;
        dw = fminf(dw, BBOXCL); dh = fminf(dh, BBOXCL);
        float pcx = dx * aw + cx, pcy = dy * ah + cy;
        float pw = expf(dw) * aw, phh = expf(dh) * ah;
        float b0 = fminf(fmaxf(pcx - 0.5f*pw , 0.f), 1216.f);
        float b1 = fminf(fmaxf(pcy - 0.5f*phh, 0.f),  800.f);
        float b2 = fminf(fmaxf(pcx + 0.5f*pw , 0.f), 1216.f);
        float b3 = fminf(fmaxf(pcy + 0.5f*phh, 0.f),  800.f);
        float* nb = &g_nbox[(n * NMSCAP + idx) * 4];
        nb[0]=b0; nb[1]=b1; nb[2]=b2; nb[3]=b3;
        float off = (float)c * 2017.0f;
        sbo[idx*4+0]=b0+off; sbo[idx*4+1]=b1+off; sbo[idx*4+2]=b2+off; sbo[idx*4+3]=b3+off;
        sws[idx] = sc; skey[idx] = key;
    }
    __syncthreads();

    int m = 0;
    for (; m < 300; m++) {
        float bs = -1e30f; unsigned bk = 0xFFFFFFFFu; int bi = -1;
        for (int k = threadIdx.x; k < K; k += 256) {
            float s = sws[k];
            if (s > bs || (s == bs && skey[k] < bk)) { bs = s; bk = skey[k]; bi = k; }
        }
        rbs[threadIdx.x]=bs; rbk[threadIdx.x]=bk; rbi[threadIdx.x]=bi;
        __syncthreads();
        for (int o = 128; o; o >>= 1) {
            if (threadIdx.x < o) {
                float s2 = rbs[threadIdx.x+o];
                if (s2 > rbs[threadIdx.x] ||
                    (s2 == rbs[threadIdx.x] && rbk[threadIdx.x+o] < rbk[threadIdx.x])) {
                    rbs[threadIdx.x]=s2; rbk[threadIdx.x]=rbk[threadIdx.x+o]; rbi[threadIdx.x]=rbi[threadIdx.x+o];
                }
            }
            __syncthreads();
        }
        bs = rbs[0]; bi = rbi[0]; bk = rbk[0];
        if (bs <= 0.0f) break;
        if (threadIdx.x == 0) {
            float* nb = &g_nbox[(n * NMSCAP + bi) * 4];
            out[n*1200 + m*4+0]=nb[0]; out[n*1200 + m*4+1]=nb[1];
            out[n*1200 + m*4+2]=nb[2]; out[n*1200 + m*4+3]=nb[3];
            out[2400 + n*300 + m] = bs;
            out[3000 + n*300 + m] = (float)((bk & 0xFFFFFFu) % 91u);
        }
        float jb0=sbo[bi*4+0], jb1=sbo[bi*4+1], jb2=sbo[bi*4+2], jb3=sbo[bi*4+3];
        float ja = (jb2-jb0)*(jb3-jb1);
        for (int k = threadIdx.x; k < K; k += 256) {
            float x0 = fmaxf(jb0, sbo[k*4+0]);
            float y0 = fmaxf(jb1, sbo[k*4+1]);
            float x1 = fminf(jb2, sbo[k*4+2]);
            float y1 = fminf(jb3, sbo[k*4+3]);
            float iw = fmaxf(x1-x0, 0.f), ih = fmaxf(y1-y0, 0.f);
            float inter = iw*ih;
            float a2 = (sbo[k*4+2]-sbo[k*4+0])*(sbo[k*4+3]-sbo[k*4+1]);
            if (inter / (ja + a2 - inter + 1e-9f) > 0.5f) sws[k] = NEGV;
        }
        __syncthreads();
    }
    for (int slot = m + (int)threadIdx.x; slot < 300; slot += 256) {
        out[n*1200 + slot*4+0]=0.f; out[n*1200 + slot*4+1]=0.f;
        out[n*1200 + slot*4+2]=0.f; out[n*1200 + slot*4+3]=0.f;
        out[2400 + n*300 + slot] = 0.f;
        out[3000 + n*300 + slot] = -1.f;
    }
}

// ------------------------- host ----------------------------------------------
extern "C" void kernel_launch(void* const* d_in, const int* in_sizes, int n_in,
                              void* d_out, int out_size)
{
    const float* f0 = (const float*)d_in[0];
    const float* f1 = (const float*)d_in[1];
    const float* f2 = (const float*)d_in[2];
    const float* f3 = (const float*)d_in[3];
    const float* f4 = (const float*)d_in[4];
    const float* cls_tw = (const float*)d_in[5];
    const float* cls_tb = (const float*)d_in[6];
    const float* cls_gs = (const float*)d_in[7];
    const float* cls_gb = (const float*)d_in[8];
    const float* cls_w  = (const float*)d_in[9];
    const float* cls_b  = (const float*)d_in[10];
    const float* reg_tw = (const float*)d_in[11];
    const float* reg_tb = (const float*)d_in[12];
    const float* reg_gs = (const float*)d_in[13];
    const float* reg_gb = (const float*)d_in[14];
    const float* reg_w  = (const float*)d_in[15];
    const float* reg_b  = (const float*)d_in[16];
    const float* anchors = (const float*)d_in[17];
    float* out = (float*)d_out;

    const long TW1 = 589824; // 256*256*9
    cudaFuncSetAttribute(nms_k, cudaFuncAttributeMaxDynamicSharedMemorySize, 122880);

    zero_cnt<<<1, 32>>>();

    const int GT = 345 * 2 * 4 * 2;

    conv_m<<<GT, 256>>>(f0, f1, f2, f3, f4, -1, 0, 0,
                        cls_tw, reg_tw, cls_tb, reg_tb,
                        nullptr, nullptr, nullptr, nullptr,
                        0, 256, 4, 2, 0);
    gn_stats_m<<<640, 256>>>(0);
    conv_m<<<GT, 256>>>(nullptr, nullptr, nullptr, nullptr, nullptr, 0, 0, 1,
                        cls_tw + TW1, reg_tw + TW1, cls_tb + 256, reg_tb + 256,
                        cls_gs, cls_gb, reg_gs, reg_gb,
                        1, 256, 4, 2, 0);
    gn_stats_m<<<640, 256>>>(1);
    conv_m<<<GT, 256>>>(nullptr, nullptr, nullptr, nullptr, nullptr, 1, 0, 0,
                        cls_tw + 2*TW1, reg_tw + 2*TW1, cls_tb + 512, reg_tb + 512,
                        cls_gs + 256, cls_gb + 256, reg_gs + 256, reg_gb + 256,
                        1, 256, 4, 2, 0);
    gn_stats_m<<<640, 256>>>(0);
    conv_m<<<GT, 256>>>(nullptr, nullptr, nullptr, nullptr, nullptr, 0, 0, 1,
                        cls_tw + 3*TW1, reg_tw + 3*TW1, cls_tb + 768, reg_tb + 768,
                        cls_gs + 512, cls_gb + 512, reg_gs + 512, reg_gb + 512,
                        1, 256, 4, 2, 0);
    gn_stats_m<<<640, 256>>>(1);

    conv_m<<<345 * 2 * 13, 256>>>(nullptr, nullptr, nullptr, nullptr, nullptr, 1, 1, 0,
                        cls_w, cls_w, cls_b, cls_b,
                        cls_gs + 768, cls_gb + 768, cls_gs + 768, cls_gb + 768,
                        1, 819, 13, 1, 0);
    conv_m<<<345 * 2 * 1, 256>>>(nullptr, nullptr, nullptr, nullptr, nullptr, 1, 2, 0,
                        reg_w, reg_w, reg_b, reg_b,
                        reg_gs + 768, reg_gb + 768, reg_gs + 768, reg_gb + 768,
                        1, 36, 1, 1, 1);

    sort_k<<<10, 1024>>>();
    nms_k<<<2, 256, 122880>>>(anchors, out);
}

// round 10
// speedup vs baseline: 1.6240x; 1.6240x over previous
#include <cuda_runtime.h>
#include <cuda_bf16.h>
#include <cstdint>

#define CAPL   65536
#define NMSCAP 5000
#define NEGV   (-1000000000.0f)
#define BBOXCL 4.135166556742356f
typedef unsigned long long ull;

// 16B-aligned bf16 weight buffers FIRST (uint4 staging loads)
#define WTOT 11943936
__device__ __align__(16) __nv_bfloat16 g_wh[WTOT];
__device__ __align__(16) __nv_bfloat16 g_wl[WTOT];

__device__ float g_t0[10376704];
__device__ float g_t1[10376704];
__device__ float g_t2[10376704];
__device__ float g_t3[10376704];
__device__ float g_reg[1459224];
__device__ float g_mu[640];
__device__ float g_var[640];
__device__ ull   g_k64[10 * CAPL];
__device__ float g_nbox[2 * NMSCAP * 4];
__device__ int   g_cnt[10];

__constant__ int  c_Hs[5]     = {100, 50, 25, 13, 7};
__constant__ int  c_Ws[5]     = {152, 76, 38, 19, 10};
__constant__ int  c_HW[5]     = {15200, 3800, 950, 247, 70};
__constant__ long c_lb[5]     = {0, 7782400, 9728000, 10214400, 10340864};
__constant__ long c_regoff[5] = {0, 1094400, 1368000, 1436400, 1454184};
__constant__ int  c_ancoff[5] = {0, 136800, 171000, 179550, 181773};
__constant__ int  c_ccum[5]   = {119, 149, 157, 159, 160};

__device__ __forceinline__ float* tb(int id) {
    switch (id) { case 0: return g_t0; case 1: return g_t1;
                  case 2: return g_t2; default: return g_t3; }
}
__device__ __forceinline__ unsigned smem_u32(const void* p) {
    unsigned a;
    asm("{ .reg .u64 t; cvta.to.shared.u64 t, %1; cvt.u32.u64 %0, t; }" : "=r"(a) : "l"(p));
    return a;
}
__device__ __forceinline__ unsigned short bfu(float v) {
    __nv_bfloat16 b = __float2bfloat16(v);
    return *(unsigned short*)&b;
}
__device__ __forceinline__ float bff(unsigned short u) {
    __nv_bfloat16 b = *(__nv_bfloat16*)&u;
    return __bfloat162float(b);
}
__device__ __forceinline__ void ldsm4(unsigned* r, unsigned a) {
    asm volatile("ldmatrix.sync.aligned.m8n8.x4.shared.b16 {%0,%1,%2,%3}, [%4];"
        : "=r"(r[0]), "=r"(r[1]), "=r"(r[2]), "=r"(r[3]) : "r"(a));
}
__device__ __forceinline__ void mma16816(float* d, const unsigned* a, const unsigned* b) {
    asm volatile("mma.sync.aligned.m16n8k16.row.col.f32.bf16.bf16.f32 "
        "{%0,%1,%2,%3}, {%4,%5,%6,%7}, {%8,%9}, {%0,%1,%2,%3};"
        : "+f"(d[0]), "+f"(d[1]), "+f"(d[2]), "+f"(d[3])
        : "r"(a[0]), "r"(a[1]), "r"(a[2]), "r"(a[3]), "r"(b[0]), "r"(b[1]));
}

__device__ __forceinline__ void emit_cand(float v, int oc, int s, int n, int lvl) {
    float sg = 1.0f / (1.0f + expf(-v));
    if (sg > 0.05f) {
        int a = oc / 91, c = oc - 91 * a;
        unsigned flat = (unsigned)((s * 9 + a) * 91 + c);
        unsigned key  = ((unsigned)lvl << 24) | flat;
        int pos = atomicAdd(&g_cnt[n * 5 + lvl], 1);
        if (pos < CAPL)
            g_k64[(long)(n * 5 + lvl) * CAPL + pos] =
                (((ull)(0xFFFFFFFFu - __float_as_uint(sg))) << 32) | key;
    }
}

// weight split/reorder: row oc, col k = icb*576 + tap*64 + icw
// segment map: [0, 8U)   = tower units 0-3 cls, 4-7 reg   (U = 589824)
//              [8U, 16U) = UNUSED padding (zeros; launches never index here)
//              [16U, 16U+1024*2304) = cls head (819 rows used)
//              tail = reg head (36 rows used, 64 padded)
__global__ void wsplit_k(const float* __restrict__ cls_tw, const float* __restrict__ reg_tw,
                         const float* __restrict__ cls_w, const float* __restrict__ reg_w)
{
    long idx = (long)blockIdx.x * 256 + threadIdx.x;
    if (idx >= WTOT) return;
    int oc, k; const float* src; int ocmax;
    if (idx < 9437184) {
        int u = (int)(idx / 589824); int r = (int)(idx - (long)u * 589824);
        oc = r / 2304; k = r - oc * 2304;
        ocmax = (u < 8) ? 256 : 0;                      // u>=8: padding, write zeros
        src = (u >= 8) ? cls_tw
            : (u >= 4 ? reg_tw + (long)(u - 4) * 589824 : cls_tw + (long)u * 589824);
    } else if (idx < 11796480) {
        int r = (int)(idx - 9437184); oc = r / 2304; k = r - oc * 2304;
        src = cls_w; ocmax = 819;
    } else {
        int r = (int)(idx - 11796480); oc = r / 2304; k = r - oc * 2304;
        src = reg_w; ocmax = 36;
    }
    float v = 0.f;
    if (oc < ocmax) {
        int icb = k / 576, t2 = k - icb * 576;
        int tap = t2 >> 6, icw = t2 & 63;
        v = src[(long)oc * 2304 + (icb * 64 + icw) * 9 + tap];
    }
    unsigned short h = bfu(v);
    g_wh[idx] = *(__nv_bfloat16*)&h;
    unsigned short lo = bfu(v - bff(h));
    g_wl[idx] = *(__nv_bfloat16*)&lo;
}

// ---- mma.sync implicit-GEMM conv: 128 px x 64 oc per CTA, K=2304 ----------
// padded smem rows: 144 bytes (72 bf16), conflict-free ldmatrix
#define SM_SCL 0
#define SM_SHB 1024
#define SM_AH  2048
#define SM_AL  20480
#define SM_BH  38912
#define SM_BL  48128
#define SM_TOT 57344

__global__ __launch_bounds__(256) void conv_t(
    const float* __restrict__ x0, const float* __restrict__ x1,
    const float* __restrict__ x2, const float* __restrict__ x3,
    const float* __restrict__ x4,
    int xpp, int ymode, int ypp, long wbA, long wbB,
    const float* __restrict__ bA, const float* __restrict__ bB,
    const float* __restrict__ gsA, const float* __restrict__ gbA,
    const float* __restrict__ gsB, const float* __restrict__ gbB,
    int gnflag, int OC, int OCT, int NBR, int brfix)
{
    extern __shared__ char sm[];
    const unsigned sb = smem_u32(sm);
    const int t = threadIdx.x;
    const int lane = t & 31;

    int bid = blockIdx.x;
    const int oct = bid % OCT;   bid /= OCT;
    const int chunk = bid % 160; bid /= 160;
    const int n = bid & 1;       bid >>= 1;
    const int br = (NBR == 2) ? bid : brfix;

    int l = 0;
    while (chunk >= c_ccum[l]) l++;
    const int pbase = (chunk - (l ? c_ccum[l - 1] : 0)) * 128;
    const int H = c_Hs[l], W = c_Ws[l], HW = c_HW[l];

    const float* x = (xpp < 0)
        ? ((l == 0) ? x0 : (l == 1) ? x1 : (l == 2) ? x2 : (l == 3) ? x3 : x4)
        : tb(br * 2 + xpp) + c_lb[l];
    const long wb = br ? wbB : wbA;
    const float* bias = br ? bB : bA;

    float* scl = (float*)(sm + SM_SCL);
    float* shb = (float*)(sm + SM_SHB);
    if (t < 256) {
        float s = 1.f, b = 0.f;
        if (gnflag) {
            const float* gs = br ? gsB : gsA;
            const float* gb = br ? gbB : gbA;
            int m = ((br * 5 + l) * 2 + n) * 32 + (t >> 3);
            s = rsqrtf(g_var[m] + 1e-5f) * gs[t];
            b = gb[t] - g_mu[m] * s;
        }
        scl[t] = s; shb[t] = b;
    }
    __syncthreads();

    // A staging mapping: warp -> 8 ic (4 pairs), lanes -> px rows
    const int icg = (t >> 5) << 3;
    int pyA[4], pxA[4]; bool pvA[4];
#pragma unroll
    for (int rb = 0; rb < 4; rb++) {
        int p = pbase + rb * 32 + lane;
        pvA[rb] = (p < HW);
        pyA[rb] = p / W;
        pxA[rb] = p - pyA[rb] * W;
    }
    // B staging mapping
    const int ocr = t >> 2, qB = t & 3;
    // warp MMA mapping: 4 M-groups x 2 N-groups
    const int w = t >> 5;
    const int px0 = (w & 3) * 32;
    const int oc0w = (w >> 2) * 32;

    float acc[2][4][4] = {};

    for (int kb = 0; kb < 36; kb++) {
        const int icb = kb / 9, tap = kb - icb * 9;
        const int dy = tap / 3 - 1, dx = tap - (tap / 3) * 3 - 1;

        // ---- stage A: 128 px x 64 ic, hi/lo, fused GN+ReLU ----
#pragma unroll
        for (int jp = 0; jp < 4; jp++) {
            const int icc = icg + jp * 2;
            const int ic = icb * 64 + icc;
            const float s0 = scl[ic], b0s = shb[ic];
            const float s1 = scl[ic + 1], b1s = shb[ic + 1];
            const float* xc0 = x + (long)(n * 256 + ic) * HW;
            const float* xc1 = xc0 + HW;
#pragma unroll
            for (int rb = 0; rb < 4; rb++) {
                float v0 = 0.f, v1 = 0.f;
                int gy = pyA[rb] + dy, gx = pxA[rb] + dx;
                if (pvA[rb] && (unsigned)gy < (unsigned)H && (unsigned)gx < (unsigned)W) {
                    long o = gy * W + gx;
                    v0 = xc0[o]; v1 = xc1[o];
                    if (gnflag) {
                        v0 = fmaxf(v0 * s0 + b0s, 0.f);
                        v1 = fmaxf(v1 * s1 + b1s, 0.f);
                    }
                }
                unsigned short h0 = bfu(v0), h1 = bfu(v1);
                unsigned short l0 = bfu(v0 - bff(h0)), l1 = bfu(v1 - bff(h1));
                const unsigned off = (unsigned)(rb * 32 + lane) * 144 + icc * 2;
                *(unsigned*)(sm + SM_AH + off) = (unsigned)h0 | ((unsigned)h1 << 16);
                *(unsigned*)(sm + SM_AL + off) = (unsigned)l0 | ((unsigned)l1 << 16);
            }
        }
        // ---- stage B: 64 oc x 64 k from pre-split weights ----
        {
            const long src = wb + (long)(oct * 64 + ocr) * 2304 + kb * 64 + qB * 16;
            uint4 h0 = *(const uint4*)(g_wh + src);
            uint4 h1 = *(const uint4*)(g_wh + src + 8);
            uint4 l0 = *(const uint4*)(g_wl + src);
            uint4 l1 = *(const uint4*)(g_wl + src + 8);
            char* dh = sm + SM_BH + ocr * 144 + qB * 32;
            char* dl = sm + SM_BL + ocr * 144 + qB * 32;
            *(uint4*)dh = h0; *(uint4*)(dh + 16) = h1;
            *(uint4*)dl = l0; *(uint4*)(dl + 16) = l1;
        }
        __syncthreads();

        // ---- 4 x k16 MMA steps ----
#pragma unroll
        for (int ks = 0; ks < 4; ks++) {
            const unsigned k2 = ks << 5;
            unsigned ah0[4], ah1[4], al0[4], al1[4];
            unsigned bh0[4], bh1[4], bl0[4], bl1[4];
            const unsigned aoff = (unsigned)(px0 + (lane & 15)) * 144 + k2 + ((lane >> 4) << 4);
            ldsm4(ah0, sb + SM_AH + aoff);
            ldsm4(ah1, sb + SM_AH + aoff + 16 * 144);
            ldsm4(al0, sb + SM_AL + aoff);
            ldsm4(al1, sb + SM_AL + aoff + 16 * 144);
            const unsigned boff = (unsigned)(oc0w + ((lane >> 4) << 3) + (lane & 7)) * 144
                                  + k2 + (((lane >> 3) & 1) << 4);
            ldsm4(bh0, sb + SM_BH + boff);
            ldsm4(bh1, sb + SM_BH + boff + 16 * 144);
            ldsm4(bl0, sb + SM_BL + boff);
            ldsm4(bl1, sb + SM_BL + boff + 16 * 144);
#pragma unroll
            for (int mt = 0; mt < 2; mt++) {
                const unsigned* ah = mt ? ah1 : ah0;
                const unsigned* al = mt ? al1 : al0;
#pragma unroll
                for (int nt = 0; nt < 4; nt++) {
                    const unsigned* bh = (nt < 2 ? bh0 : bh1) + (nt & 1) * 2;
                    const unsigned* bl = (nt < 2 ? bl0 : bl1) + (nt & 1) * 2;
                    float* d = acc[mt][nt];
                    mma16816(d, ah, bh);
                    mma16816(d, ah, bl);
                    mma16816(d, al, bh);
                }
            }
        }
        __syncthreads();
    }

    // ---- epilogue ----
    const int prow = pbase + px0 + (lane >> 2);
    const int c0 = oct * 64 + oc0w + (lane & 3) * 2;
    float* y = (ymode == 0) ? tb(br * 2 + ypp) + c_lb[l]
             : (ymode == 2) ? g_reg + c_regoff[l] : nullptr;
    const int ocst = (ymode == 2) ? 36 : 256;
#pragma unroll
    for (int mt = 0; mt < 2; mt++) {
        const int p1 = prow + mt * 16, p2 = p1 + 8;
#pragma unroll
        for (int nt = 0; nt < 4; nt++) {
            const int oc = c0 + nt * 8;
            if (oc >= OC) continue;
            const bool o1 = (oc + 1 < OC);
            const float bv0 = bias[oc], bv1 = o1 ? bias[oc + 1] : 0.f;
            float v00 = acc[mt][nt][0] + bv0, v01 = acc[mt][nt][1] + bv1;
            float v10 = acc[mt][nt][2] + bv0, v11 = acc[mt][nt][3] + bv1;
            if (ymode == 1) {
                if (p1 < HW) {
                    if (v00 > -3.0f) emit_cand(v00, oc, p1, n, l);
                    if (o1 && v01 > -3.0f) emit_cand(v01, oc + 1, p1, n, l);
                }
                if (p2 < HW) {
                    if (v10 > -3.0f) emit_cand(v10, oc, p2, n, l);
                    if (o1 && v11 > -3.0f) emit_cand(v11, oc + 1, p2, n, l);
                }
            } else {
                float* yb0 = y + (long)(n * ocst + oc) * HW;
                float* yb1 = yb0 + HW;
                if (p1 < HW) { yb0[p1] = v00; if (o1) yb1[p1] = v01; }
                if (p2 < HW) { yb0[p2] = v10; if (o1) yb1[p2] = v11; }
            }
        }
    }
}

__global__ __launch_bounds__(256) void gn_stats_m(int pp)
{
    int b = blockIdx.x;
    const int g = b % 32; b /= 32;
    const int n = b % 2;  b /= 2;
    const int l = b % 5;  b /= 5;
    const int br = b;
    const int HW = c_HW[l];
    const float* p = tb(br * 2 + pp) + c_lb[l] + (long)(n * 256 + g * 8) * HW;
    const int total = 8 * HW;
    double s = 0.0, ss = 0.0;
    for (int i = threadIdx.x; i < total; i += 256) {
        float v = p[i]; s += v; ss += (double)v * (double)v;
    }
    __shared__ double rs[256], rq[256];
    rs[threadIdx.x] = s; rq[threadIdx.x] = ss;
    __syncthreads();
    for (int o = 128; o; o >>= 1) {
        if (threadIdx.x < o) { rs[threadIdx.x] += rs[threadIdx.x+o]; rq[threadIdx.x] += rq[threadIdx.x+o]; }
        __syncthreads();
    }
    if (threadIdx.x == 0) {
        int m = ((br * 5 + l) * 2 + n) * 32 + g;
        double mu = rs[0] / total;
        g_mu[m] = (float)mu;
        g_var[m] = (float)(rq[0] / total - mu * mu);
    }
}

__global__ void zero_cnt() { if (threadIdx.x < 10) g_cnt[threadIdx.x] = 0; }

__global__ __launch_bounds__(1024) void sort_k()
{
    const int b = blockIdx.x;
    ull* v = g_k64 + (long)b * CAPL;
    int cnt = g_cnt[b]; if (cnt > CAPL) cnt = CAPL;
    if (cnt <= 1) return;
    int n2 = 1; while (n2 < cnt) n2 <<= 1;
    for (int i = cnt + threadIdx.x; i < n2; i += 1024) v[i] = ~0ull;
    __syncthreads();
    for (int k = 2; k <= n2; k <<= 1)
        for (int j = k >> 1; j > 0; j >>= 1) {
            for (int i = threadIdx.x; i < n2; i += 1024) {
                int ixj = i ^ j;
                if (ixj > i) {
                    ull a = v[i], c2 = v[ixj];
                    if ((a > c2) == ((i & k) == 0)) { v[i] = c2; v[ixj] = a; }
                }
            }
            __syncthreads();
        }
}

extern __shared__ unsigned char s_raw[];

__global__ __launch_bounds__(256) void nms_k(const float* __restrict__ anc,
                                             float* __restrict__ out)
{
    const int n = blockIdx.x;
    float*    sws  = (float*)s_raw;
    float*    sbo  = (float*)s_raw + 5008;
    unsigned* skey = (unsigned*)((float*)s_raw + 25008);
    __shared__ float rbs[256];
    __shared__ unsigned rbk[256];
    __shared__ int rbi[256];

    int Ls[5], offs[5], K = 0;
    for (int l = 0; l < 5; l++) {
        int c = g_cnt[n * 5 + l];
        if (c > CAPL) c = CAPL;
        if (c > 1000) c = 1000;
        offs[l] = K; Ls[l] = c; K += c;
    }
    for (int idx = threadIdx.x; idx < K; idx += 256) {
        int l = 0;
        while (l < 4 && idx >= offs[l] + Ls[l]) l++;
        ull v = g_k64[(long)(n * 5 + l) * CAPL + (idx - offs[l])];
        unsigned key = (unsigned)v;
        float sc = __uint_as_float(0xFFFFFFFFu - (unsigned)(v >> 32));
        int flat = (int)(key & 0xFFFFFFu);
        int ai = flat / 91, c = flat - ai * 91;
        int sidx = ai / 9, a = ai - sidx * 9;
        int HW = c_HW[l];
        const float* rp = g_reg + c_regoff[l] + (long)(n * 36 + a * 4) * HW + sidx;
        float dx = rp[0], dy = rp[HW], dw = rp[2*HW], dh = rp[3*HW];
        int gi = c_ancoff[l] + ai;
        float ax0 = anc[4*gi], ay0 = anc[4*gi+1], ax1 = anc[4*gi+2], ay1 = anc[4*gi+3];
        float aw = ax1 - ax0, ah = ay1 - ay0;
        float cx = ax0 + 0.5f * aw, cy = ay0 + 0.5f * ah;
        dw = fminf(dw, BBOXCL); dh = fminf(dh, BBOXCL);
        float pcx = dx * aw + cx, pcy = dy * ah + cy;
        float pw = expf(dw) * aw, phh = expf(dh) * ah;
        float b0 = fminf(fmaxf(pcx - 0.5f*pw , 0.f), 1216.f);
        float b1 = fminf(fmaxf(pcy - 0.5f*phh, 0.f),  800.f);
        float b2 = fminf(fmaxf(pcx + 0.5f*pw , 0.f), 1216.f);
        float b3 = fminf(fmaxf(pcy + 0.5f*phh, 0.f),  800.f);
        float* nb = &g_nbox[(n * NMSCAP + idx) * 4];
        nb[0]=b0; nb[1]=b1; nb[2]=b2; nb[3]=b3;
        float off = (float)c * 2017.0f;
        sbo[idx*4+0]=b0+off; sbo[idx*4+1]=b1+off; sbo[idx*4+2]=b2+off; sbo[idx*4+3]=b3+off;
        sws[idx] = sc; skey[idx] = key;
    }
    __syncthreads();

    int m = 0;
    for (; m < 300; m++) {
        float bs = -1e30f; unsigned bk = 0xFFFFFFFFu; int bi = -1;
        for (int k = threadIdx.x; k < K; k += 256) {
            float s = sws[k];
            if (s > bs || (s == bs && skey[k] < bk)) { bs = s; bk = skey[k]; bi = k; }
        }
        rbs[threadIdx.x]=bs; rbk[threadIdx.x]=bk; rbi[threadIdx.x]=bi;
        __syncthreads();
        for (int o = 128; o; o >>= 1) {
            if (threadIdx.x < o) {
                float s2 = rbs[threadIdx.x+o];
                if (s2 > rbs[threadIdx.x] ||
                    (s2 == rbs[threadIdx.x] && rbk[threadIdx.x+o] < rbk[threadIdx.x])) {
                    rbs[threadIdx.x]=s2; rbk[threadIdx.x]=rbk[threadIdx.x+o]; rbi[threadIdx.x]=rbi[threadIdx.x+o];
                }
            }
            __syncthreads();
        }
        bs = rbs[0]; bi = rbi[0]; bk = rbk[0];
        if (bs <= 0.0f) break;
        if (threadIdx.x == 0) {
            float* nb = &g_nbox[(n * NMSCAP + bi) * 4];
            out[n*1200 + m*4+0]=nb[0]; out[n*1200 + m*4+1]=nb[1];
            out[n*1200 + m*4+2]=nb[2]; out[n*1200 + m*4+3]=nb[3];
            out[2400 + n*300 + m] = bs;
            out[3000 + n*300 + m] = (float)((bk & 0xFFFFFFu) % 91u);
        }
        float jb0=sbo[bi*4+0], jb1=sbo[bi*4+1], jb2=sbo[bi*4+2], jb3=sbo[bi*4+3];
        float ja = (jb2-jb0)*(jb3-jb1);
        for (int k = threadIdx.x; k < K; k += 256) {
            float x0 = fmaxf(jb0, sbo[k*4+0]);
            float y0 = fmaxf(jb1, sbo[k*4+1]);
            float x1 = fminf(jb2, sbo[k*4+2]);
            float y1 = fminf(jb3, sbo[k*4+3]);
            float iw = fmaxf(x1-x0, 0.f), ih = fmaxf(y1-y0, 0.f);
            float inter = iw*ih;
            float a2 = (sbo[k*4+2]-sbo[k*4+0])*(sbo[k*4+3]-sbo[k*4+1]);
            if (inter / (ja + a2 - inter + 1e-9f) > 0.5f) sws[k] = NEGV;
        }
        __syncthreads();
    }
    for (int slot = m + (int)threadIdx.x; slot < 300; slot += 256) {
        out[n*1200 + slot*4+0]=0.f; out[n*1200 + slot*4+1]=0.f;
        out[n*1200 + slot*4+2]=0.f; out[n*1200 + slot*4+3]=0.f;
        out[2400 + n*300 + slot] = 0.f;
        out[3000 + n*300 + slot] = -1.f;
    }
}

extern "C" void kernel_launch(void* const* d_in, const int* in_sizes, int n_in,
                              void* d_out, int out_size)
{
    const float* f0 = (const float*)d_in[0];
    const float* f1 = (const float*)d_in[1];
    const float* f2 = (const float*)d_in[2];
    const float* f3 = (const float*)d_in[3];
    const float* f4 = (const float*)d_in[4];
    const float* cls_tw = (const float*)d_in[5];
    const float* cls_tb = (const float*)d_in[6];
    const float* cls_gs = (const float*)d_in[7];
    const float* cls_gb = (const float*)d_in[8];
    const float* cls_w  = (const float*)d_in[9];
    const float* cls_b  = (const float*)d_in[10];
    const float* reg_tw = (const float*)d_in[11];
    const float* reg_tb = (const float*)d_in[12];
    const float* reg_gs = (const float*)d_in[13];
    const float* reg_gb = (const float*)d_in[14];
    const float* reg_w  = (const float*)d_in[15];
    const float* reg_b  = (const float*)d_in[16];
    const float* anchors = (const float*)d_in[17];
    float* out = (float*)d_out;

    const long U = 589824;
    cudaFuncSetAttribute(nms_k, cudaFuncAttributeMaxDynamicSharedMemorySize, 122880);
    cudaFuncSetAttribute(conv_t, cudaFuncAttributeMaxDynamicSharedMemorySize, SM_TOT);

    zero_cnt<<<1, 32>>>();
    wsplit_k<<<(WTOT + 255) / 256, 256>>>(cls_tw, reg_tw, cls_w, reg_w);

    const int GT = 4 * 160 * 2 * 2;   // OCT=4, chunks, n, br
    conv_t<<<GT, 256, SM_TOT>>>(f0, f1, f2, f3, f4, -1, 0, 0, 0, 4*U,
                                cls_tb, reg_tb, nullptr, nullptr, nullptr, nullptr,
                                0, 256, 4, 2, 0);
    gn_stats_m<<<640, 256>>>(0);
    conv_t<<<GT, 256, SM_TOT>>>(nullptr, nullptr, nullptr, nullptr, nullptr, 0, 0, 1, 1*U, 5*U,
                                cls_tb + 256, reg_tb + 256, cls_gs, cls_gb, reg_gs, reg_gb,
                                1, 256, 4, 2, 0);
    gn_stats_m<<<640, 256>>>(1);
    conv_t<<<GT, 256, SM_TOT>>>(nullptr, nullptr, nullptr, nullptr, nullptr, 1, 0, 0, 2*U, 6*U,
                                cls_tb + 512, reg_tb + 512,
                                cls_gs + 256, cls_gb + 256, reg_gs + 256, reg_gb + 256,
                                1, 256, 4, 2, 0);
    gn_stats_m<<<640, 256>>>(0);
    conv_t<<<GT, 256, SM_TOT>>>(nullptr, nullptr, nullptr, nullptr, nullptr, 0, 0, 1, 3*U, 7*U,
                                cls_tb + 768, reg_tb + 768,
                                cls_gs + 512, cls_gb + 512, reg_gs + 512, reg_gb + 512,
                                1, 256, 4, 2, 0);
    gn_stats_m<<<640, 256>>>(1);

    // cls head: emit candidates. OC=819, OCT=13
    conv_t<<<13 * 160 * 2, 256, SM_TOT>>>(nullptr, nullptr, nullptr, nullptr, nullptr,
                                1, 1, 0, 9437184L, 9437184L,
                                cls_b, cls_b,
                                cls_gs + 768, cls_gb + 768, cls_gs + 768, cls_gb + 768,
                                1, 819, 13, 1, 0);
    // reg head: OC=36, OCT=1, br=1
    conv_t<<<160 * 2, 256, SM_TOT>>>(nullptr, nullptr, nullptr, nullptr, nullptr,
                                1, 2, 0, 11796480L, 11796480L,
                                reg_b, reg_b,
                                reg_gs + 768, reg_gb + 768, reg_gs + 768, reg_gb + 768,
                                1, 36, 1, 1, 1);

    sort_k<<<10, 1024>>>();
    nms_k<<<2, 256, 122880>>>(anchors, out);
}

// round 11
// speedup vs baseline: 1.9970x; 1.2297x over previous
#include <cuda_runtime.h>
#include <cuda_bf16.h>
#include <cstdint>

#define CAPL   65536
#define NMSCAP 5000
#define NEGV   (-1000000000.0f)
#define BBOXCL 4.135166556742356f
typedef unsigned long long ull;

#define WTOT 11943936
__device__ __align__(16) __nv_bfloat16 g_wh[WTOT];
__device__ __align__(16) __nv_bfloat16 g_wl[WTOT];
// fp32 conv outputs [n][ch][px], one per branch
__device__ float g_t0[10376704];
__device__ float g_t1[10376704];
// bf16 hi/lo activations [n][px][ch], per branch
__device__ __align__(16) __nv_bfloat16 g_ah0[10376704];
__device__ __align__(16) __nv_bfloat16 g_al0[10376704];
__device__ __align__(16) __nv_bfloat16 g_ah1[10376704];
__device__ __align__(16) __nv_bfloat16 g_al1[10376704];
__device__ float g_reg[1459224];
__device__ float g_mu[640];
__device__ float g_var[640];
__device__ ull   g_k64[10 * CAPL];
__device__ float g_nbox[2 * NMSCAP * 4];
__device__ int   g_cnt[10];

__constant__ int  c_Hs[5]     = {100, 50, 25, 13, 7};
__constant__ int  c_Ws[5]     = {152, 76, 38, 19, 10};
__constant__ int  c_HW[5]     = {15200, 3800, 950, 247, 70};
__constant__ long c_lb[5]     = {0, 7782400, 9728000, 10214400, 10340864};
__constant__ long c_regoff[5] = {0, 1094400, 1368000, 1436400, 1454184};
__constant__ int  c_ancoff[5] = {0, 136800, 171000, 179550, 181773};
__constant__ int  c_ccum[5]   = {119, 149, 157, 159, 160};
__constant__ int  c_c32[5]    = {475, 594, 624, 632, 635};

__device__ __forceinline__ unsigned smem_u32(const void* p) {
    unsigned a;
    asm("{ .reg .u64 t; cvta.to.shared.u64 t, %1; cvt.u32.u64 %0, t; }" : "=r"(a) : "l"(p));
    return a;
}
__device__ __forceinline__ unsigned short bfu(float v) {
    __nv_bfloat16 b = __float2bfloat16(v);
    return *(unsigned short*)&b;
}
__device__ __forceinline__ float bff(unsigned short u) {
    __nv_bfloat16 b = *(__nv_bfloat16*)&u;
    return __bfloat162float(b);
}
__device__ __forceinline__ void ldsm4(unsigned* r, unsigned a) {
    asm volatile("ldmatrix.sync.aligned.m8n8.x4.shared.b16 {%0,%1,%2,%3}, [%4];"
        : "=r"(r[0]), "=r"(r[1]), "=r"(r[2]), "=r"(r[3]) : "r"(a));
}
__device__ __forceinline__ void mma16816(float* d, const unsigned* a, const unsigned* b) {
    asm volatile("mma.sync.aligned.m16n8k16.row.col.f32.bf16.bf16.f32 "
        "{%0,%1,%2,%3}, {%4,%5,%6,%7}, {%8,%9}, {%0,%1,%2,%3};"
        : "+f"(d[0]), "+f"(d[1]), "+f"(d[2]), "+f"(d[3])
        : "r"(a[0]), "r"(a[1]), "r"(a[2]), "r"(a[3]), "r"(b[0]), "r"(b[1]));
}

__device__ __forceinline__ void emit_cand(float v, int oc, int s, int n, int lvl) {
    float sg = 1.0f / (1.0f + expf(-v));
    if (sg > 0.05f) {
        int a = oc / 91, c = oc - 91 * a;
        unsigned flat = (unsigned)((s * 9 + a) * 91 + c);
        unsigned key  = ((unsigned)lvl << 24) | flat;
        int pos = atomicAdd(&g_cnt[n * 5 + lvl], 1);
        if (pos < CAPL)
            g_k64[(long)(n * 5 + lvl) * CAPL + pos] =
                (((ull)(0xFFFFFFFFu - __float_as_uint(sg))) << 32) | key;
    }
}

// weight split/reorder (R10-proven): row oc, col k = icb*576 + tap*64 + icw
__global__ void wsplit_k(const float* __restrict__ cls_tw, const float* __restrict__ reg_tw,
                         const float* __restrict__ cls_w, const float* __restrict__ reg_w)
{
    long idx = (long)blockIdx.x * 256 + threadIdx.x;
    if (idx >= WTOT) return;
    int oc, k; const float* src; int ocmax;
    if (idx < 9437184) {
        int u = (int)(idx / 589824); int r = (int)(idx - (long)u * 589824);
        oc = r / 2304; k = r - oc * 2304;
        ocmax = (u < 8) ? 256 : 0;
        src = (u >= 8) ? cls_tw
            : (u >= 4 ? reg_tw + (long)(u - 4) * 589824 : cls_tw + (long)u * 589824);
    } else if (idx < 11796480) {
        int r = (int)(idx - 9437184); oc = r / 2304; k = r - oc * 2304;
        src = cls_w; ocmax = 819;
    } else {
        int r = (int)(idx - 11796480); oc = r / 2304; k = r - oc * 2304;
        src = reg_w; ocmax = 36;
    }
    float v = 0.f;
    if (oc < ocmax) {
        int icb = k / 576, t2 = k - icb * 576;
        int tap = t2 >> 6, icw = t2 & 63;
        v = src[(long)oc * 2304 + (icb * 64 + icw) * 9 + tap];
    }
    unsigned short h = bfu(v);
    g_wh[idx] = *(__nv_bfloat16*)&h;
    unsigned short lo = bfu(v - bff(h));
    g_wl[idx] = *(__nv_bfloat16*)&lo;
}

// ---- cvt: fp32 [n][ch][px] (+GN+ReLU) -> bf16 hi/lo [n][px][ch] ------------
__global__ __launch_bounds__(256) void cvt_k(
    const float* __restrict__ x0, const float* __restrict__ x1,
    const float* __restrict__ x2, const float* __restrict__ x3,
    const float* __restrict__ x4, int ext, int gnflag,
    const float* __restrict__ gsA, const float* __restrict__ gbA,
    const float* __restrict__ gsB, const float* __restrict__ gbB)
{
    __shared__ float ts[256][33];
    __shared__ float scl[256], shb[256];
    const int t = threadIdx.x;
    int cid = blockIdx.x;
    const int n = blockIdx.y, br = blockIdx.z;
    int l = 0; while (cid >= c_c32[l]) l++;
    const int p0 = (cid - (l ? c_c32[l - 1] : 0)) * 32;
    const int HW = c_HW[l];
    const float* x = ext
        ? ((l == 0) ? x0 : (l == 1) ? x1 : (l == 2) ? x2 : (l == 3) ? x3 : x4)
        : (br ? g_t1 : g_t0) + c_lb[l];
    __nv_bfloat16* ah = (br ? g_ah1 : g_ah0) + c_lb[l];
    __nv_bfloat16* al = (br ? g_al1 : g_al0) + c_lb[l];
    if (gnflag) {
        const float* gs = br ? gsB : gsA;
        const float* gb = br ? gbB : gbA;
        int m = ((br * 5 + l) * 2 + n) * 32 + (t >> 3);
        float s = rsqrtf(g_var[m] + 1e-5f) * gs[t];
        scl[t] = s; shb[t] = gb[t] - g_mu[m] * s;
    } else { scl[t] = 1.f; shb[t] = 0.f; }
    __syncthreads();
    const int pxl = t & 31, chb = t >> 5;
#pragma unroll 4
    for (int cb = 0; cb < 32; cb++) {
        int ch = cb * 8 + chb;
        int p = p0 + pxl;
        float v = 0.f;
        if (p < HW) {
            v = x[(long)(n * 256 + ch) * HW + p];
            if (gnflag) v = fmaxf(v * scl[ch] + shb[ch], 0.f);
        }
        ts[ch][pxl] = v;
    }
    __syncthreads();
    const int px = t >> 3, chq = t & 7;
    const int p = p0 + px;
    if (p < HW) {
        long base = ((long)(n * HW + p)) * 256 + chq * 32;
        unsigned hbuf[16], lbuf[16];
#pragma unroll
        for (int i = 0; i < 16; i++) {
            float f0 = ts[chq * 32 + 2 * i][px];
            float f1 = ts[chq * 32 + 2 * i + 1][px];
            unsigned short h0 = bfu(f0), h1 = bfu(f1);
            unsigned short q0 = bfu(f0 - bff(h0)), q1 = bfu(f1 - bff(h1));
            hbuf[i] = (unsigned)h0 | ((unsigned)h1 << 16);
            lbuf[i] = (unsigned)q0 | ((unsigned)q1 << 16);
        }
#pragma unroll
        for (int i = 0; i < 4; i++) {
            ((uint4*)(ah + base))[i] = ((uint4*)hbuf)[i];
            ((uint4*)(al + base))[i] = ((uint4*)lbuf)[i];
        }
    }
}

// ---- mma.sync implicit-GEMM conv: 128 px x 64 oc per CTA, K=2304 ----------
#define SM_AH  2048
#define SM_AL  20480
#define SM_BH  38912
#define SM_BL  48128
#define SM_TOT 57344

__global__ __launch_bounds__(256) void conv_t(
    int ymode, int xbr0, long wbA, long wbB,
    const float* __restrict__ bA, const float* __restrict__ bB,
    int OC, int OCT, int NBR, int brfix)
{
    extern __shared__ char sm[];
    const unsigned sb = smem_u32(sm);
    const int t = threadIdx.x, lane = t & 31;

    int bid = blockIdx.x;
    const int oct = bid % OCT;   bid /= OCT;
    const int chunk = bid % 160; bid /= 160;
    const int n = bid & 1;       bid >>= 1;
    const int br = (NBR == 2) ? bid : brfix;

    int l = 0;
    while (chunk >= c_ccum[l]) l++;
    const int pbase = (chunk - (l ? c_ccum[l - 1] : 0)) * 128;
    const int H = c_Hs[l], W = c_Ws[l], HW = c_HW[l];

    const int abr = xbr0 ? 0 : br;
    const long wb = br ? wbB : wbA;
    const float* bias = br ? bB : bA;

    // A staging: thread -> (row rA, plane hA); 8x LDG.128 + 8x STS.128 per kb
    const int rA = t & 127, hA = t >> 7;
    const int pA = pbase + rA;
    const bool pvA = (pA < HW);
    const int pyA = pvA ? pA / W : 0;
    const int pxA = pA - pyA * W;
    const __nv_bfloat16* aplane =
        hA ? (abr ? g_al1 : g_al0) : (abr ? g_ah1 : g_ah0);
    const __nv_bfloat16* abase = aplane + c_lb[l] + (long)n * HW * 256;
    char* adst = sm + (hA ? SM_AL : SM_AH) + rA * 144;

    const int ocr = t >> 2, qB = t & 3;
    const int w = t >> 5;
    const int px0 = (w & 3) * 32;
    const int oc0w = (w >> 2) * 32;

    float acc[2][4][4] = {};

    for (int kb = 0; kb < 36; kb++) {
        const int icb = kb / 9, tap = kb - icb * 9;
        const int dy = tap / 3 - 1, dx = tap - (tap / 3) * 3 - 1;

        // ---- stage A ----
        {
            int gy = pyA + dy, gx = pxA + dx;
            if (pvA && (unsigned)gy < (unsigned)H && (unsigned)gx < (unsigned)W) {
                const uint4* s = (const uint4*)(abase + (long)(pA + dy * W + dx) * 256 + icb * 64);
#pragma unroll
                for (int j = 0; j < 8; j++) ((uint4*)adst)[j] = s[j];
            } else {
                uint4 z = make_uint4(0, 0, 0, 0);
#pragma unroll
                for (int j = 0; j < 8; j++) ((uint4*)adst)[j] = z;
            }
        }
        // ---- stage B ----
        {
            const long src = wb + (long)(oct * 64 + ocr) * 2304 + kb * 64 + qB * 16;
            uint4 h0 = *(const uint4*)(g_wh + src);
            uint4 h1 = *(const uint4*)(g_wh + src + 8);
            uint4 l0 = *(const uint4*)(g_wl + src);
            uint4 l1 = *(const uint4*)(g_wl + src + 8);
            char* dh = sm + SM_BH + ocr * 144 + qB * 32;
            char* dl = sm + SM_BL + ocr * 144 + qB * 32;
            *(uint4*)dh = h0; *(uint4*)(dh + 16) = h1;
            *(uint4*)dl = l0; *(uint4*)(dl + 16) = l1;
        }
        __syncthreads();

        // ---- 4 x k16 MMA steps ----
#pragma unroll
        for (int ks = 0; ks < 4; ks++) {
            const unsigned k2 = ks << 5;
            unsigned ah0[4], ah1[4], al0[4], al1[4];
            unsigned bh0[4], bh1[4], bl0[4], bl1[4];
            const unsigned aoff = (unsigned)(px0 + (lane & 15)) * 144 + k2 + ((lane >> 4) << 4);
            ldsm4(ah0, sb + SM_AH + aoff);
            ldsm4(ah1, sb + SM_AH + aoff + 16 * 144);
            ldsm4(al0, sb + SM_AL + aoff);
            ldsm4(al1, sb + SM_AL + aoff + 16 * 144);
            const unsigned boff = (unsigned)(oc0w + ((lane >> 4) << 3) + (lane & 7)) * 144
                                  + k2 + (((lane >> 3) & 1) << 4);
            ldsm4(bh0, sb + SM_BH + boff);
            ldsm4(bh1, sb + SM_BH + boff + 16 * 144);
            ldsm4(bl0, sb + SM_BL + boff);
            ldsm4(bl1, sb + SM_BL + boff + 16 * 144);
#pragma unroll
            for (int mt = 0; mt < 2; mt++) {
                const unsigned* ah = mt ? ah1 : ah0;
                const unsigned* al = mt ? al1 : al0;
#pragma unroll
                for (int nt = 0; nt < 4; nt++) {
                    const unsigned* bh = (nt < 2 ? bh0 : bh1) + (nt & 1) * 2;
                    const unsigned* bl = (nt < 2 ? bl0 : bl1) + (nt & 1) * 2;
                    float* d = acc[mt][nt];
                    mma16816(d, ah, bh);
                    mma16816(d, ah, bl);
                    mma16816(d, al, bh);
                }
            }
        }
        __syncthreads();
    }

    // ---- epilogue ----
    const int prow = pbase + px0 + (lane >> 2);
    const int c0 = oct * 64 + oc0w + (lane & 3) * 2;
    float* y = (ymode == 0) ? (br ? g_t1 : g_t0) + c_lb[l]
             : (ymode == 2) ? g_reg + c_regoff[l] : nullptr;
    const int ocst = (ymode == 2) ? 36 : 256;
#pragma unroll
    for (int mt = 0; mt < 2; mt++) {
        const int p1 = prow + mt * 16, p2 = p1 + 8;
#pragma unroll
        for (int nt = 0; nt < 4; nt++) {
            const int oc = c0 + nt * 8;
            if (oc >= OC) continue;
            const bool o1 = (oc + 1 < OC);
            const float bv0 = bias[oc], bv1 = o1 ? bias[oc + 1] : 0.f;
            float v00 = acc[mt][nt][0] + bv0, v01 = acc[mt][nt][1] + bv1;
            float v10 = acc[mt][nt][2] + bv0, v11 = acc[mt][nt][3] + bv1;
            if (ymode == 1) {
                if (p1 < HW) {
                    if (v00 > -3.0f) emit_cand(v00, oc, p1, n, l);
                    if (o1 && v01 > -3.0f) emit_cand(v01, oc + 1, p1, n, l);
                }
                if (p2 < HW) {
                    if (v10 > -3.0f) emit_cand(v10, oc, p2, n, l);
                    if (o1 && v11 > -3.0f) emit_cand(v11, oc + 1, p2, n, l);
                }
            } else {
                float* yb0 = y + (long)(n * ocst + oc) * HW;
                float* yb1 = yb0 + HW;
                if (p1 < HW) { yb0[p1] = v00; if (o1) yb1[p1] = v01; }
                if (p2 < HW) { yb0[p2] = v10; if (o1) yb1[p2] = v11; }
            }
        }
    }
}

__global__ __launch_bounds__(256) void gn_stats_m()
{
    int b = blockIdx.x;
    const int g = b % 32; b /= 32;
    const int n = b % 2;  b /= 2;
    const int l = b % 5;  b /= 5;
    const int br = b;
    const int HW = c_HW[l];
    const float* p = (br ? g_t1 : g_t0) + c_lb[l] + (long)(n * 256 + g * 8) * HW;
    const int total = 8 * HW;
    double s = 0.0, ss = 0.0;
    for (int i = threadIdx.x; i < total; i += 256) {
        float v = p[i]; s += v; ss += (double)v * (double)v;
    }
    __shared__ double rs[256], rq[256];
    rs[threadIdx.x] = s; rq[threadIdx.x] = ss;
    __syncthreads();
    for (int o = 128; o; o >>= 1) {
        if (threadIdx.x < o) { rs[threadIdx.x] += rs[threadIdx.x+o]; rq[threadIdx.x] += rq[threadIdx.x+o]; }
        __syncthreads();
    }
    if (threadIdx.x == 0) {
        int m = ((br * 5 + l) * 2 + n) * 32 + g;
        double mu = rs[0] / total;
        g_mu[m] = (float)mu;
        g_var[m] = (float)(rq[0] / total - mu * mu);
    }
}

__global__ void zero_cnt() { if (threadIdx.x < 10) g_cnt[threadIdx.x] = 0; }

__global__ __launch_bounds__(1024) void sort_k()
{
    const int b = blockIdx.x;
    ull* v = g_k64 + (long)b * CAPL;
    int cnt = g_cnt[b]; if (cnt > CAPL) cnt = CAPL;
    if (cnt <= 1) return;
    int n2 = 1; while (n2 < cnt) n2 <<= 1;
    for (int i = cnt + threadIdx.x; i < n2; i += 1024) v[i] = ~0ull;
    __syncthreads();
    for (int k = 2; k <= n2; k <<= 1)
        for (int j = k >> 1; j > 0; j >>= 1) {
            for (int i = threadIdx.x; i < n2; i += 1024) {
                int ixj = i ^ j;
                if (ixj > i) {
                    ull a = v[i], c2 = v[ixj];
                    if ((a > c2) == ((i & k) == 0)) { v[i] = c2; v[ixj] = a; }
                }
            }
            __syncthreads();
        }
}

extern __shared__ unsigned char s_raw[];

__global__ __launch_bounds__(256) void nms_k(const float* __restrict__ anc,
                                             float* __restrict__ out)
{
    const int n = blockIdx.x;
    float*    sws  = (float*)s_raw;
    float*    sbo  = (float*)s_raw + 5008;
    unsigned* skey = (unsigned*)((float*)s_raw + 25008);
    __shared__ float rbs[256];
    __shared__ unsigned rbk[256];
    __shared__ int rbi[256];

    int Ls[5], offs[5], K = 0;
    for (int l = 0; l < 5; l++) {
        int c = g_cnt[n * 5 + l];
        if (c > CAPL) c = CAPL;
        if (c > 1000) c = 1000;
        offs[l] = K; Ls[l] = c; K += c;
    }
    for (int idx = threadIdx.x; idx < K; idx += 256) {
        int l = 0;
        while (l < 4 && idx >= offs[l] + Ls[l]) l++;
        ull v = g_k64[(long)(n * 5 + l) * CAPL + (idx - offs[l])];
        unsigned key = (unsigned)v;
        float sc = __uint_as_float(0xFFFFFFFFu - (unsigned)(v >> 32));
        int flat = (int)(key & 0xFFFFFFu);
        int ai = flat / 91, c = flat - ai * 91;
        int sidx = ai / 9, a = ai - sidx * 9;
        int HW = c_HW[l];
        const float* rp = g_reg + c_regoff[l] + (long)(n * 36 + a * 4) * HW + sidx;
        float dx = rp[0], dy = rp[HW], dw = rp[2*HW], dh = rp[3*HW];
        int gi = c_ancoff[l] + ai;
        float ax0 = anc[4*gi], ay0 = anc[4*gi+1], ax1 = anc[4*gi+2], ay1 = anc[4*gi+3];
        float aw = ax1 - ax0, ah = ay1 - ay0;
        float cx = ax0 + 0.5f * aw, cy = ay0 + 0.5f * ah;
        dw = fminf(dw, BBOXCL); dh = fminf(dh, BBOXCL);
        float pcx = dx * aw + cx, pcy = dy * ah + cy;
        float pw = expf(dw) * aw, phh = expf(dh) * ah;
        float b0 = fminf(fmaxf(pcx - 0.5f*pw , 0.f), 1216.f);
        float b1 = fminf(fmaxf(pcy - 0.5f*phh, 0.f),  800.f);
        float b2 = fminf(fmaxf(pcx + 0.5f*pw , 0.f), 1216.f);
        float b3 = fminf(fmaxf(pcy + 0.5f*phh, 0.f),  800.f);
        float* nb = &g_nbox[(n * NMSCAP + idx) * 4];
        nb[0]=b0; nb[1]=b1; nb[2]=b2; nb[3]=b3;
        float off = (float)c * 2017.0f;
        sbo[idx*4+0]=b0+off; sbo[idx*4+1]=b1+off; sbo[idx*4+2]=b2+off; sbo[idx*4+3]=b3+off;
        sws[idx] = sc; skey[idx] = key;
    }
    __syncthreads();

    int m = 0;
    for (; m < 300; m++) {
        float bs = -1e30f; unsigned bk = 0xFFFFFFFFu; int bi = -1;
        for (int k = threadIdx.x; k < K; k += 256) {
            float s = sws[k];
            if (s > bs || (s == bs && skey[k] < bk)) { bs = s; bk = skey[k]; bi = k; }
        }
        rbs[threadIdx.x]=bs; rbk[threadIdx.x]=bk; rbi[threadIdx.x]=bi;
        __syncthreads();
        for (int o = 128; o; o >>= 1) {
            if (threadIdx.x < o) {
                float s2 = rbs[threadIdx.x+o];
                if (s2 > rbs[threadIdx.x] ||
                    (s2 == rbs[threadIdx.x] && rbk[threadIdx.x+o] < rbk[threadIdx.x])) {
                    rbs[threadIdx.x]=s2; rbk[threadIdx.x]=rbk[threadIdx.x+o]; rbi[threadIdx.x]=rbi[threadIdx.x+o];
                }
            }
            __syncthreads();
        }
        bs = rbs[0]; bi = rbi[0]; bk = rbk[0];
        if (bs <= 0.0f) break;
        if (threadIdx.x == 0) {
            float* nb = &g_nbox[(n * NMSCAP + bi) * 4];
            out[n*1200 + m*4+0]=nb[0]; out[n*1200 + m*4+1]=nb[1];
            out[n*1200 + m*4+2]=nb[2]; out[n*1200 + m*4+3]=nb[3];
            out[2400 + n*300 + m] = bs;
            out[3000 + n*300 + m] = (float)((bk & 0xFFFFFFu) % 91u);
        }
        float jb0=sbo[bi*4+0], jb1=sbo[bi*4+1], jb2=sbo[bi*4+2], jb3=sbo[bi*4+3];
        float ja = (jb2-jb0)*(jb3-jb1);
        for (int k = threadIdx.x; k < K; k += 256) {
            float x0 = fmaxf(jb0, sbo[k*4+0]);
            float y0 = fmaxf(jb1, sbo[k*4+1]);
            float x1 = fminf(jb2, sbo[k*4+2]);
            float y1 = fminf(jb3, sbo[k*4+3]);
            float iw = fmaxf(x1-x0, 0.f), ih = fmaxf(y1-y0, 0.f);
            float inter = iw*ih;
            float a2 = (sbo[k*4+2]-sbo[k*4+0])*(sbo[k*4+3]-sbo[k*4+1]);
            if (inter / (ja + a2 - inter + 1e-9f) > 0.5f) sws[k] = NEGV;
        }
        __syncthreads();
    }
    for (int slot = m + (int)threadIdx.x; slot < 300; slot += 256) {
        out[n*1200 + slot*4+0]=0.f; out[n*1200 + slot*4+1]=0.f;
        out[n*1200 + slot*4+2]=0.f; out[n*1200 + slot*4+3]=0.f;
        out[2400 + n*300 + slot] = 0.f;
        out[3000 + n*300 + slot] = -1.f;
    }
}

extern "C" void kernel_launch(void* const* d_in, const int* in_sizes, int n_in,
                              void* d_out, int out_size)
{
    const float* f0 = (const float*)d_in[0];
    const float* f1 = (const float*)d_in[1];
    const float* f2 = (const float*)d_in[2];
    const float* f3 = (const float*)d_in[3];
    const float* f4 = (const float*)d_in[4];
    const float* cls_tw = (const float*)d_in[5];
    const float* cls_tb = (const float*)d_in[6];
    const float* cls_gs = (const float*)d_in[7];
    const float* cls_gb = (const float*)d_in[8];
    const float* cls_w  = (const float*)d_in[9];
    const float* cls_b  = (const float*)d_in[10];
    const float* reg_tw = (const float*)d_in[11];
    const float* reg_tb = (const float*)d_in[12];
    const float* reg_gs = (const float*)d_in[13];
    const float* reg_gb = (const float*)d_in[14];
    const float* reg_w  = (const float*)d_in[15];
    const float* reg_b  = (const float*)d_in[16];
    const float* anchors = (const float*)d_in[17];
    float* out = (float*)d_out;

    const long U = 589824;
    cudaFuncSetAttribute(nms_k, cudaFuncAttributeMaxDynamicSharedMemorySize, 122880);
    cudaFuncSetAttribute(conv_t, cudaFuncAttributeMaxDynamicSharedMemorySize, SM_TOT);

    zero_cnt<<<1, 32>>>();
    wsplit_k<<<(WTOT + 255) / 256, 256>>>(cls_tw, reg_tw, cls_w, reg_w);

    // feats -> bf16 (branch-0 buffers; layer-0 conv forces abr=0)
    dim3 gf(635, 2, 1);
    cvt_k<<<gf, 256>>>(f0, f1, f2, f3, f4, 1, 0,
                       nullptr, nullptr, nullptr, nullptr);

    const int GT = 4 * 160 * 2 * 2;
    dim3 gc(635, 2, 2);

    conv_t<<<GT, 256, SM_TOT>>>(0, 1, 0, 4*U, cls_tb, reg_tb, 256, 4, 2, 0);
    gn_stats_m<<<640, 256>>>();
    cvt_k<<<gc, 256>>>(nullptr, nullptr, nullptr, nullptr, nullptr, 0, 1,
                       cls_gs, cls_gb, reg_gs, reg_gb);

    conv_t<<<GT, 256, SM_TOT>>>(0, 0, 1*U, 5*U, cls_tb + 256, reg_tb + 256, 256, 4, 2, 0);
    gn_stats_m<<<640, 256>>>();
    cvt_k<<<gc, 256>>>(nullptr, nullptr, nullptr, nullptr, nullptr, 0, 1,
                       cls_gs + 256, cls_gb + 256, reg_gs + 256, reg_gb + 256);

    conv_t<<<GT, 256, SM_TOT>>>(0, 0, 2*U, 6*U, cls_tb + 512, reg_tb + 512, 256, 4, 2, 0);
    gn_stats_m<<<640, 256>>>();
    cvt_k<<<gc, 256>>>(nullptr, nullptr, nullptr, nullptr, nullptr, 0, 1,
                       cls_gs + 512, cls_gb + 512, reg_gs + 512, reg_gb + 512);

    conv_t<<<GT, 256, SM_TOT>>>(0, 0, 3*U, 7*U, cls_tb + 768, reg_tb + 768, 256, 4, 2, 0);
    gn_stats_m<<<640, 256>>>();
    cvt_k<<<gc, 256>>>(nullptr, nullptr, nullptr, nullptr, nullptr, 0, 1,
                       cls_gs + 768, cls_gb + 768, reg_gs + 768, reg_gb + 768);

    // cls head (br 0), candidate emit; reg head (br 1)
    conv_t<<<13 * 160 * 2, 256, SM_TOT>>>(1, 0, 9437184L, 9437184L,
                                          cls_b, cls_b, 819, 13, 1, 0);
    conv_t<<<160 * 2, 256, SM_TOT>>>(2, 0, 11796480L, 11796480L,
                                     reg_b, reg_b, 36, 1, 1, 1);

    sort_k<<<10, 1024>>>();
    nms_k<<<2, 256, 122880>>>(anchors, out);
}

// round 12
// speedup vs baseline: 2.4809x; 1.2424x over previous
#include <cuda_runtime.h>
#include <cuda_bf16.h>
#include <cstdint>

#define CAPL   65536
#define NMSCAP 5000
#define NEGV   (-1000000000.0f)
#define BBOXCL 4.135166556742356f
typedef unsigned long long ull;

#define WTOT 11943936
__device__ __align__(16) __nv_bfloat16 g_wh[WTOT];
__device__ __align__(16) __nv_bfloat16 g_wl[WTOT];
__device__ float g_t0[10376704];
__device__ float g_t1[10376704];
__device__ __align__(16) __nv_bfloat16 g_ah0[10376704];
__device__ __align__(16) __nv_bfloat16 g_al0[10376704];
__device__ __align__(16) __nv_bfloat16 g_ah1[10376704];
__device__ __align__(16) __nv_bfloat16 g_al1[10376704];
__device__ float g_reg[1459224];
__device__ float g_mu[640];
__device__ float g_var[640];
__device__ ull   g_k64[10 * CAPL];
__device__ float g_nbox[2 * NMSCAP * 4];
__device__ int   g_cnt[10];

__constant__ int  c_Hs[5]     = {100, 50, 25, 13, 7};
__constant__ int  c_Ws[5]     = {152, 76, 38, 19, 10};
__constant__ int  c_HW[5]     = {15200, 3800, 950, 247, 70};
__constant__ long c_lb[5]     = {0, 7782400, 9728000, 10214400, 10340864};
__constant__ long c_regoff[5] = {0, 1094400, 1368000, 1436400, 1454184};
__constant__ int  c_ancoff[5] = {0, 136800, 171000, 179550, 181773};
__constant__ int  c_ccum[5]   = {119, 149, 157, 159, 160};
__constant__ int  c_c32[5]    = {475, 594, 624, 632, 635};

__device__ __forceinline__ unsigned smem_u32(const void* p) {
    unsigned a;
    asm("{ .reg .u64 t; cvta.to.shared.u64 t, %1; cvt.u32.u64 %0, t; }" : "=r"(a) : "l"(p));
    return a;
}
__device__ __forceinline__ unsigned short bfu(float v) {
    __nv_bfloat16 b = __float2bfloat16(v);
    return *(unsigned short*)&b;
}
__device__ __forceinline__ float bff(unsigned short u) {
    __nv_bfloat16 b = *(__nv_bfloat16*)&u;
    return __bfloat162float(b);
}
__device__ __forceinline__ void ldsm4(unsigned* r, unsigned a) {
    asm volatile("ldmatrix.sync.aligned.m8n8.x4.shared.b16 {%0,%1,%2,%3}, [%4];"
        : "=r"(r[0]), "=r"(r[1]), "=r"(r[2]), "=r"(r[3]) : "r"(a));
}
__device__ __forceinline__ void mma16816(float* d, const unsigned* a, const unsigned* b) {
    asm volatile("mma.sync.aligned.m16n8k16.row.col.f32.bf16.bf16.f32 "
        "{%0,%1,%2,%3}, {%4,%5,%6,%7}, {%8,%9}, {%0,%1,%2,%3};"
        : "+f"(d[0]), "+f"(d[1]), "+f"(d[2]), "+f"(d[3])
        : "r"(a[0]), "r"(a[1]), "r"(a[2]), "r"(a[3]), "r"(b[0]), "r"(b[1]));
}

__device__ __forceinline__ void emit_cand(float v, int oc, int s, int n, int lvl) {
    float sg = 1.0f / (1.0f + expf(-v));
    if (sg > 0.05f) {
        int a = oc / 91, c = oc - 91 * a;
        unsigned flat = (unsigned)((s * 9 + a) * 91 + c);
        unsigned key  = ((unsigned)lvl << 24) | flat;
        int pos = atomicAdd(&g_cnt[n * 5 + lvl], 1);
        if (pos < CAPL)
            g_k64[(long)(n * 5 + lvl) * CAPL + pos] =
                (((ull)(0xFFFFFFFFu - __float_as_uint(sg))) << 32) | key;
    }
}

__global__ void wsplit_k(const float* __restrict__ cls_tw, const float* __restrict__ reg_tw,
                         const float* __restrict__ cls_w, const float* __restrict__ reg_w)
{
    long idx = (long)blockIdx.x * 256 + threadIdx.x;
    if (idx >= WTOT) return;
    int oc, k; const float* src; int ocmax;
    if (idx < 9437184) {
        int u = (int)(idx / 589824); int r = (int)(idx - (long)u * 589824);
        oc = r / 2304; k = r - oc * 2304;
        ocmax = (u < 8) ? 256 : 0;
        src = (u >= 8) ? cls_tw
            : (u >= 4 ? reg_tw + (long)(u - 4) * 589824 : cls_tw + (long)u * 589824);
    } else if (idx < 11796480) {
        int r = (int)(idx - 9437184); oc = r / 2304; k = r - oc * 2304;
        src = cls_w; ocmax = 819;
    } else {
        int r = (int)(idx - 11796480); oc = r / 2304; k = r - oc * 2304;
        src = reg_w; ocmax = 36;
    }
    float v = 0.f;
    if (oc < ocmax) {
        int icb = k / 576, t2 = k - icb * 576;
        int tap = t2 >> 6, icw = t2 & 63;
        v = src[(long)oc * 2304 + (icb * 64 + icw) * 9 + tap];
    }
    unsigned short h = bfu(v);
    g_wh[idx] = *(__nv_bfloat16*)&h;
    unsigned short lo = bfu(v - bff(h));
    g_wl[idx] = *(__nv_bfloat16*)&lo;
}

// ---- cvt: fp32 [n][ch][px] (+GN+ReLU) -> bf16 hi/lo [n][px][ch] ------------
__global__ __launch_bounds__(256) void cvt_k(
    const float* __restrict__ x0, const float* __restrict__ x1,
    const float* __restrict__ x2, const float* __restrict__ x3,
    const float* __restrict__ x4, int ext, int gnflag,
    const float* __restrict__ gsA, const float* __restrict__ gbA,
    const float* __restrict__ gsB, const float* __restrict__ gbB)
{
    __shared__ float ts[256][33];
    __shared__ float scl[256], shb[256];
    const int t = threadIdx.x;
    int cid = blockIdx.x;
    const int n = blockIdx.y, br = blockIdx.z;
    int l = 0; while (cid >= c_c32[l]) l++;
    const int p0 = (cid - (l ? c_c32[l - 1] : 0)) * 32;
    const int HW = c_HW[l];
    const float* x = ext
        ? ((l == 0) ? x0 : (l == 1) ? x1 : (l == 2) ? x2 : (l == 3) ? x3 : x4)
        : (br ? g_t1 : g_t0) + c_lb[l];
    __nv_bfloat16* ah = (br ? g_ah1 : g_ah0) + c_lb[l];
    __nv_bfloat16* al = (br ? g_al1 : g_al0) + c_lb[l];
    if (gnflag) {
        const float* gs = br ? gsB : gsA;
        const float* gb = br ? gbB : gbA;
        int m = ((br * 5 + l) * 2 + n) * 32 + (t >> 3);
        float s = rsqrtf(g_var[m] + 1e-5f) * gs[t];
        scl[t] = s; shb[t] = gb[t] - g_mu[m] * s;
    } else { scl[t] = 1.f; shb[t] = 0.f; }
    __syncthreads();
    const int pxl = t & 31, chb = t >> 5;
#pragma unroll 4
    for (int cb = 0; cb < 32; cb++) {
        int ch = cb * 8 + chb;
        int p = p0 + pxl;
        float v = 0.f;
        if (p < HW) {
            v = x[(long)(n * 256 + ch) * HW + p];
            if (gnflag) v = fmaxf(v * scl[ch] + shb[ch], 0.f);
        }
        ts[ch][pxl] = v;
    }
    __syncthreads();
    const int px = t >> 3, chq = t & 7;
    const int p = p0 + px;
    if (p < HW) {
        long base = ((long)(n * HW + p)) * 256 + chq * 32;
        unsigned hbuf[16], lbuf[16];
#pragma unroll
        for (int i = 0; i < 16; i++) {
            float f0 = ts[chq * 32 + 2 * i][px];
            float f1 = ts[chq * 32 + 2 * i + 1][px];
            unsigned short h0 = bfu(f0), h1 = bfu(f1);
            unsigned short q0 = bfu(f0 - bff(h0)), q1 = bfu(f1 - bff(h1));
            hbuf[i] = (unsigned)h0 | ((unsigned)h1 << 16);
            lbuf[i] = (unsigned)q0 | ((unsigned)q1 << 16);
        }
#pragma unroll
        for (int i = 0; i < 4; i++) {
            ((uint4*)(ah + base))[i] = ((uint4*)hbuf)[i];
            ((uint4*)(al + base))[i] = ((uint4*)lbuf)[i];
        }
    }
}

// ---- mma.sync implicit-GEMM conv: 128 px x 128 oc per CTA, K=2304 ---------
// 8 warps = 4M x 2N; each warp 32px x 64oc. padded 144B smem rows.
#define SM_AH  0
#define SM_AL  18432
#define SM_BH  36864
#define SM_BL  55296
#define SM_TOT 73728

__global__ __launch_bounds__(256, 2) void conv_t(
    int ymode, int xbr0, long wbA, long wbB,
    const float* __restrict__ bA, const float* __restrict__ bB,
    int OC, int OCPAD, int OCT, int NBR, int brfix)
{
    extern __shared__ char sm[];
    const unsigned sb = smem_u32(sm);
    const int t = threadIdx.x, lane = t & 31;

    int bid = blockIdx.x;
    const int oct = bid % OCT;   bid /= OCT;
    const int chunk = bid % 160; bid /= 160;
    const int n = bid & 1;       bid >>= 1;
    const int br = (NBR == 2) ? bid : brfix;

    int l = 0;
    while (chunk >= c_ccum[l]) l++;
    const int pbase = (chunk - (l ? c_ccum[l - 1] : 0)) * 128;
    const int H = c_Hs[l], W = c_Ws[l], HW = c_HW[l];

    const int abr = xbr0 ? 0 : br;
    const long wb = br ? wbB : wbA;
    const float* bias = br ? bB : bA;

    // A staging: thread -> (row rA, plane hA)
    const int rA = t & 127, hA = t >> 7;
    const int pA = pbase + rA;
    const bool pvA = (pA < HW);
    const int pyA = pvA ? pA / W : 0;
    const int pxA = pA - pyA * W;
    const __nv_bfloat16* aplane =
        hA ? (abr ? g_al1 : g_al0) : (abr ? g_ah1 : g_ah0);
    const __nv_bfloat16* abase = aplane + c_lb[l] + (long)n * HW * 256;
    char* adst = sm + (hA ? SM_AL : SM_AH) + rA * 144;

    // B staging: thread -> (row rB 0..127, half qB2 0..1 of 64k)
    const int rB = t >> 1, qB2 = t & 1;
    const int ocrow = oct * 128 + rB;
    const bool bok = (ocrow < OCPAD);
    const long bsrc0 = wb + (long)ocrow * 2304 + qB2 * 32;
    char* bdh = sm + SM_BH + rB * 144 + qB2 * 64;
    char* bdl = sm + SM_BL + rB * 144 + qB2 * 64;

    // warp MMA mapping: 4 M x 2 N
    const int w = t >> 5;
    const int px0 = (w & 3) * 32;
    const int oc0w = (w >> 2) * 64;

    float acc[2][8][4] = {};

    for (int kb = 0; kb < 36; kb++) {
        const int icb = kb / 9, tap = kb - icb * 9;
        const int dy = tap / 3 - 1, dx = tap - (tap / 3) * 3 - 1;

        // ---- stage A ----
        {
            int gy = pyA + dy, gx = pxA + dx;
            if (pvA && (unsigned)gy < (unsigned)H && (unsigned)gx < (unsigned)W) {
                const uint4* s = (const uint4*)(abase + (long)(pA + dy * W + dx) * 256 + icb * 64);
#pragma unroll
                for (int j = 0; j < 8; j++) ((uint4*)adst)[j] = s[j];
            } else {
                uint4 z = make_uint4(0, 0, 0, 0);
#pragma unroll
                for (int j = 0; j < 8; j++) ((uint4*)adst)[j] = z;
            }
        }
        // ---- stage B (guarded) ----
        if (bok) {
            const long src = bsrc0 + kb * 64;
#pragma unroll
            for (int j = 0; j < 4; j++) {
                ((uint4*)bdh)[j] = *(const uint4*)(g_wh + src + j * 8);
                ((uint4*)bdl)[j] = *(const uint4*)(g_wl + src + j * 8);
            }
        } else {
            uint4 z = make_uint4(0, 0, 0, 0);
#pragma unroll
            for (int j = 0; j < 4; j++) { ((uint4*)bdh)[j] = z; ((uint4*)bdl)[j] = z; }
        }
        __syncthreads();

        // ---- 4 x k16 MMA steps ----
#pragma unroll
        for (int ks = 0; ks < 4; ks++) {
            const unsigned k2 = ks << 5;
            unsigned ah0[4], ah1[4], al0[4], al1[4];
            const unsigned aoff = (unsigned)(px0 + (lane & 15)) * 144 + k2 + ((lane >> 4) << 4);
            ldsm4(ah0, sb + SM_AH + aoff);
            ldsm4(ah1, sb + SM_AH + aoff + 16 * 144);
            ldsm4(al0, sb + SM_AL + aoff);
            ldsm4(al1, sb + SM_AL + aoff + 16 * 144);
#pragma unroll
            for (int nh = 0; nh < 2; nh++) {
                unsigned bh[8], bl[8];
                const unsigned boff = (unsigned)(oc0w + nh * 32 + ((lane >> 4) << 3) + (lane & 7)) * 144
                                      + k2 + (((lane >> 3) & 1) << 4);
                ldsm4(bh,     sb + SM_BH + boff);
                ldsm4(bh + 4, sb + SM_BH + boff + 16 * 144);
                ldsm4(bl,     sb + SM_BL + boff);
                ldsm4(bl + 4, sb + SM_BL + boff + 16 * 144);
#pragma unroll
                for (int mt = 0; mt < 2; mt++) {
                    const unsigned* ah = mt ? ah1 : ah0;
                    const unsigned* al = mt ? al1 : al0;
#pragma unroll
                    for (int nt = 0; nt < 4; nt++) {
                        const unsigned* bhp = bh + nt * 2;
                        const unsigned* blp = bl + nt * 2;
                        float* d = acc[mt][nh * 4 + nt];
                        mma16816(d, ah, bhp);
                        mma16816(d, ah, blp);
                        mma16816(d, al, bhp);
                    }
                }
            }
        }
        __syncthreads();
    }

    // ---- epilogue ----
    const int prow = pbase + px0 + (lane >> 2);
    const int c0 = oct * 128 + oc0w + (lane & 3) * 2;
    float* y = (ymode == 0) ? (br ? g_t1 : g_t0) + c_lb[l]
             : (ymode == 2) ? g_reg + c_regoff[l] : nullptr;
    const int ocst = (ymode == 2) ? 36 : 256;
#pragma unroll
    for (int mt = 0; mt < 2; mt++) {
        const int p1 = prow + mt * 16, p2 = p1 + 8;
#pragma unroll
        for (int nt = 0; nt < 8; nt++) {
            const int oc = c0 + nt * 8;
            if (oc >= OC) continue;
            const bool o1 = (oc + 1 < OC);
            const float bv0 = bias[oc], bv1 = o1 ? bias[oc + 1] : 0.f;
            float v00 = acc[mt][nt][0] + bv0, v01 = acc[mt][nt][1] + bv1;
            float v10 = acc[mt][nt][2] + bv0, v11 = acc[mt][nt][3] + bv1;
            if (ymode == 1) {
                if (p1 < HW) {
                    if (v00 > -3.0f) emit_cand(v00, oc, p1, n, l);
                    if (o1 && v01 > -3.0f) emit_cand(v01, oc + 1, p1, n, l);
                }
                if (p2 < HW) {
                    if (v10 > -3.0f) emit_cand(v10, oc, p2, n, l);
                    if (o1 && v11 > -3.0f) emit_cand(v11, oc + 1, p2, n, l);
                }
            } else {
                float* yb0 = y + (long)(n * ocst + oc) * HW;
                float* yb1 = yb0 + HW;
                if (p1 < HW) { yb0[p1] = v00; if (o1) yb1[p1] = v01; }
                if (p2 < HW) { yb0[p2] = v10; if (o1) yb1[p2] = v11; }
            }
        }
    }
}

__global__ __launch_bounds__(256) void gn_stats_m()
{
    int b = blockIdx.x;
    const int g = b % 32; b /= 32;
    const int n = b % 2;  b /= 2;
    const int l = b % 5;  b /= 5;
    const int br = b;
    const int HW = c_HW[l];
    const float* p = (br ? g_t1 : g_t0) + c_lb[l] + (long)(n * 256 + g * 8) * HW;
    const int total = 8 * HW;
    double s = 0.0, ss = 0.0;
    for (int i = threadIdx.x; i < total; i += 256) {
        float v = p[i]; s += v; ss += (double)v * (double)v;
    }
    __shared__ double rs[256], rq[256];
    rs[threadIdx.x] = s; rq[threadIdx.x] = ss;
    __syncthreads();
    for (int o = 128; o; o >>= 1) {
        if (threadIdx.x < o) { rs[threadIdx.x] += rs[threadIdx.x+o]; rq[threadIdx.x] += rq[threadIdx.x+o]; }
        __syncthreads();
    }
    if (threadIdx.x == 0) {
        int m = ((br * 5 + l) * 2 + n) * 32 + g;
        double mu = rs[0] / total;
        g_mu[m] = (float)mu;
        g_var[m] = (float)(rq[0] / total - mu * mu);
    }
}

__global__ void zero_cnt() { if (threadIdx.x < 10) g_cnt[threadIdx.x] = 0; }

__global__ __launch_bounds__(1024) void sort_k()
{
    const int b = blockIdx.x;
    ull* v = g_k64 + (long)b * CAPL;
    int cnt = g_cnt[b]; if (cnt > CAPL) cnt = CAPL;
    if (cnt <= 1) return;
    int n2 = 1; while (n2 < cnt) n2 <<= 1;
    for (int i = cnt + threadIdx.x; i < n2; i += 1024) v[i] = ~0ull;
    __syncthreads();
    for (int k = 2; k <= n2; k <<= 1)
        for (int j = k >> 1; j > 0; j >>= 1) {
            for (int i = threadIdx.x; i < n2; i += 1024) {
                int ixj = i ^ j;
                if (ixj > i) {
                    ull a = v[i], c2 = v[ixj];
                    if ((a > c2) == ((i & k) == 0)) { v[i] = c2; v[ixj] = a; }
                }
            }
            __syncthreads();
        }
}

extern __shared__ unsigned char s_raw[];

__global__ __launch_bounds__(256) void nms_k(const float* __restrict__ anc,
                                             float* __restrict__ out)
{
    const int n = blockIdx.x;
    float*    sws  = (float*)s_raw;
    float*    sbo  = (float*)s_raw + 5008;
    unsigned* skey = (unsigned*)((float*)s_raw + 25008);
    __shared__ float rbs[256];
    __shared__ unsigned rbk[256];
    __shared__ int rbi[256];

    int Ls[5], offs[5], K = 0;
    for (int l = 0; l < 5; l++) {
        int c = g_cnt[n * 5 + l];
        if (c > CAPL) c = CAPL;
        if (c > 1000) c = 1000;
        offs[l] = K; Ls[l] = c; K += c;
    }
    for (int idx = threadIdx.x; idx < K; idx += 256) {
        int l = 0;
        while (l < 4 && idx >= offs[l] + Ls[l]) l++;
        ull v = g_k64[(long)(n * 5 + l) * CAPL + (idx - offs[l])];
        unsigned key = (unsigned)v;
        float sc = __uint_as_float(0xFFFFFFFFu - (unsigned)(v >> 32));
        int flat = (int)(key & 0xFFFFFFu);
        int ai = flat / 91, c = flat - ai * 91;
        int sidx = ai / 9, a = ai - sidx * 9;
        int HW = c_HW[l];
        const float* rp = g_reg + c_regoff[l] + (long)(n * 36 + a * 4) * HW + sidx;
        float dx = rp[0], dy = rp[HW], dw = rp[2*HW], dh = rp[3*HW];
        int gi = c_ancoff[l] + ai;
        float ax0 = anc[4*gi], ay0 = anc[4*gi+1], ax1 = anc[4*gi+2], ay1 = anc[4*gi+3];
        float aw = ax1 - ax0, ah = ay1 - ay0;
        float cx = ax0 + 0.5f * aw, cy = ay0 + 0.5f * ah;
        dw = fminf(dw, BBOXCL); dh = fminf(dh, BBOXCL);
        float pcx = dx * aw + cx, pcy = dy * ah + cy;
        float pw = expf(dw) * aw, phh = expf(dh) * ah;
        float b0 = fminf(fmaxf(pcx - 0.5f*pw , 0.f), 1216.f);
        float b1 = fminf(fmaxf(pcy - 0.5f*phh, 0.f),  800.f);
        float b2 = fminf(fmaxf(pcx + 0.5f*pw , 0.f), 1216.f);
        float b3 = fminf(fmaxf(pcy + 0.5f*phh, 0.f),  800.f);
        float* nb = &g_nbox[(n * NMSCAP + idx) * 4];
        nb[0]=b0; nb[1]=b1; nb[2]=b2; nb[3]=b3;
        float off = (float)c * 2017.0f;
        sbo[idx*4+0]=b0+off; sbo[idx*4+1]=b1+off; sbo[idx*4+2]=b2+off; sbo[idx*4+3]=b3+off;
        sws[idx] = sc; skey[idx] = key;
    }
    __syncthreads();

    int m = 0;
    for (; m < 300; m++) {
        float bs = -1e30f; unsigned bk = 0xFFFFFFFFu; int bi = -1;
        for (int k = threadIdx.x; k < K; k += 256) {
            float s = sws[k];
            if (s > bs || (s == bs && skey[k] < bk)) { bs = s; bk = skey[k]; bi = k; }
        }
        rbs[threadIdx.x]=bs; rbk[threadIdx.x]=bk; rbi[threadIdx.x]=bi;
        __syncthreads();
        for (int o = 128; o; o >>= 1) {
            if (threadIdx.x < o) {
                float s2 = rbs[threadIdx.x+o];
                if (s2 > rbs[threadIdx.x] ||
                    (s2 == rbs[threadIdx.x] && rbk[threadIdx.x+o] < rbk[threadIdx.x])) {
                    rbs[threadIdx.x]=s2; rbk[threadIdx.x]=rbk[threadIdx.x+o]; rbi[threadIdx.x]=rbi[threadIdx.x+o];
                }
            }
            __syncthreads();
        }
        bs = rbs[0]; bi = rbi[0]; bk = rbk[0];
        if (bs <= 0.0f) break;
        if (threadIdx.x == 0) {
            float* nb = &g_nbox[(n * NMSCAP + bi) * 4];
            out[n*1200 + m*4+0]=nb[0]; out[n*1200 + m*4+1]=nb[1];
            out[n*1200 + m*4+2]=nb[2]; out[n*1200 + m*4+3]=nb[3];
            out[2400 + n*300 + m] = bs;
            out[3000 + n*300 + m] = (float)((bk & 0xFFFFFFu) % 91u);
        }
        float jb0=sbo[bi*4+0], jb1=sbo[bi*4+1], jb2=sbo[bi*4+2], jb3=sbo[bi*4+3];
        float ja = (jb2-jb0)*(jb3-jb1);
        for (int k = threadIdx.x; k < K; k += 256) {
            float x0 = fmaxf(jb0, sbo[k*4+0]);
            float y0 = fmaxf(jb1, sbo[k*4+1]);
            float x1 = fminf(jb2, sbo[k*4+2]);
            float y1 = fminf(jb3, sbo[k*4+3]);
            float iw = fmaxf(x1-x0, 0.f), ih = fmaxf(y1-y0, 0.f);
            float inter = iw*ih;
            float a2 = (sbo[k*4+2]-sbo[k*4+0])*(sbo[k*4+3]-sbo[k*4+1]);
            if (inter / (ja + a2 - inter + 1e-9f) > 0.5f) sws[k] = NEGV;
        }
        __syncthreads();
    }
    for (int slot = m + (int)threadIdx.x; slot < 300; slot += 256) {
        out[n*1200 + slot*4+0]=0.f; out[n*1200 + slot*4+1]=0.f;
        out[n*1200 + slot*4+2]=0.f; out[n*1200 + slot*4+3]=0.f;
        out[2400 + n*300 + slot] = 0.f;
        out[3000 + n*300 + slot] = -1.f;
    }
}

extern "C" void kernel_launch(void* const* d_in, const int* in_sizes, int n_in,
                              void* d_out, int out_size)
{
    const float* f0 = (const float*)d_in[0];
    const float* f1 = (const float*)d_in[1];
    const float* f2 = (const float*)d_in[2];
    const float* f3 = (const float*)d_in[3];
    const float* f4 = (const float*)d_in[4];
    const float* cls_tw = (const float*)d_in[5];
    const float* cls_tb = (const float*)d_in[6];
    const float* cls_gs = (const float*)d_in[7];
    const float* cls_gb = (const float*)d_in[8];
    const float* cls_w  = (const float*)d_in[9];
    const float* cls_b  = (const float*)d_in[10];
    const float* reg_tw = (const float*)d_in[11];
    const float* reg_tb = (const float*)d_in[12];
    const float* reg_gs = (const float*)d_in[13];
    const float* reg_gb = (const float*)d_in[14];
    const float* reg_w  = (const float*)d_in[15];
    const float* reg_b  = (const float*)d_in[16];
    const float* anchors = (const float*)d_in[17];
    float* out = (float*)d_out;

    const long U = 589824;
    cudaFuncSetAttribute(nms_k, cudaFuncAttributeMaxDynamicSharedMemorySize, 122880);
    cudaFuncSetAttribute(conv_t, cudaFuncAttributeMaxDynamicSharedMemorySize, SM_TOT);

    zero_cnt<<<1, 32>>>();
    wsplit_k<<<(WTOT + 255) / 256, 256>>>(cls_tw, reg_tw, cls_w, reg_w);

    dim3 gf(635, 2, 1);
    cvt_k<<<gf, 256>>>(f0, f1, f2, f3, f4, 1, 0,
                       nullptr, nullptr, nullptr, nullptr);

    const int GT = 2 * 160 * 2 * 2;   // OCT=2 x chunks x n x br
    dim3 gc(635, 2, 2);

    conv_t<<<GT, 256, SM_TOT>>>(0, 1, 0, 4*U, cls_tb, reg_tb, 256, 256, 2, 2, 0);
    gn_stats_m<<<640, 256>>>();
    cvt_k<<<gc, 256>>>(nullptr, nullptr, nullptr, nullptr, nullptr, 0, 1,
                       cls_gs, cls_gb, reg_gs, reg_gb);

    conv_t<<<GT, 256, SM_TOT>>>(0, 0, 1*U, 5*U, cls_tb + 256, reg_tb + 256, 256, 256, 2, 2, 0);
    gn_stats_m<<<640, 256>>>();
    cvt_k<<<gc, 256>>>(nullptr, nullptr, nullptr, nullptr, nullptr, 0, 1,
                       cls_gs + 256, cls_gb + 256, reg_gs + 256, reg_gb + 256);

    conv_t<<<GT, 256, SM_TOT>>>(0, 0, 2*U, 6*U, cls_tb + 512, reg_tb + 512, 256, 256, 2, 2, 0);
    gn_stats_m<<<640, 256>>>();
    cvt_k<<<gc, 256>>>(nullptr, nullptr, nullptr, nullptr, nullptr, 0, 1,
                       cls_gs + 512, cls_gb + 512, reg_gs + 512, reg_gb + 512);

    conv_t<<<GT, 256, SM_TOT>>>(0, 0, 3*U, 7*U, cls_tb + 768, reg_tb + 768, 256, 256, 2, 2, 0);
    gn_stats_m<<<640, 256>>>();
    cvt_k<<<gc, 256>>>(nullptr, nullptr, nullptr, nullptr, nullptr, 0, 1,
                       cls_gs + 768, cls_gb + 768, reg_gs + 768, reg_gb + 768);

    // cls head: 7 oc-tiles of 128 (1024 padded rows); candidate emit
    conv_t<<<7 * 160 * 2, 256, SM_TOT>>>(1, 0, 9437184L, 9437184L,
                                         cls_b, cls_b, 819, 1024, 7, 1, 0);
    // reg head: 1 tile, 64 padded rows
    conv_t<<<160 * 2, 256, SM_TOT>>>(2, 0, 11796480L, 11796480L,
                                     reg_b, reg_b, 36, 64, 1, 1, 1);

    sort_k<<<10, 1024>>>();
    nms_k<<<2, 256, 122880>>>(anchors, out);
}